// round 5
// baseline (speedup 1.0000x reference)
#include <cuda_runtime.h>
#include <math.h>

#define NNODES 300000
#define DMODEL 128
#define KNBR 5

// ---------------- scratch (device globals; no runtime allocation) ----------
__device__ float g_rowsum[NNODES];
__device__ unsigned char g_mask[NNODES * KNBR];
__device__ int g_valid_mode;   // 0 = int32 bools, 1 = uint8 bools, 2 = float bools
__device__ float g_Q[NNODES * DMODEL];
__device__ float g_K[NNODES * DMODEL];
__device__ float g_V[NNODES * DMODEL];
__device__ float g_O[NNODES * DMODEL];
__device__ float g_T[NNODES * DMODEL];
__device__ float g_X1[NNODES * DMODEL];
__device__ float g_X2[NNODES * DMODEL];
__device__ float g_H[NNODES * 2 * DMODEL];

// ---------------- nbr_valid encoding detection -----------------------------
// valid[i][0] is always true (deg >= 1). Scan 2048 32-bit words (8KB, safe for
// all candidate encodings of the 1.5M-element buffer):
//   int32 bools  -> every word is 0 or 1
//   float bools  -> every word is 0 or 0x3f800000
//   uint8 bools  -> words are packed 0/1 bytes; with random deg in [1,5] some
//                   word has a nonzero high byte -> fails both tests above
__global__ void detect_valid_kernel(const unsigned int* v) {
    int all01 = 1, allf = 1;
    for (int t = 0; t < 2048; ++t) {
        unsigned int x = v[t];
        if (x > 1u) all01 = 0;
        if (x != 0u && x != 0x3f800000u) allf = 0;
    }
    g_valid_mode = all01 ? 0 : (allf ? 2 : 1);
}

// ---------------- per-row feat sum (for the ==0 mask) -----------------------
__global__ void rowsum_kernel(const float* __restrict__ feat) {
    int row = blockIdx.x * 8 + (threadIdx.x >> 5);
    if (row >= NNODES) return;
    int lane = threadIdx.x & 31;
    float4 v = ((const float4*)(feat + (size_t)row * DMODEL))[lane];
    float s = v.x + v.y + v.z + v.w;
    #pragma unroll
    for (int o = 16; o > 0; o >>= 1) s += __shfl_xor_sync(0xffffffffu, s, o);
    if (lane == 0) g_rowsum[row] = s;
}

// ---------------- per-edge mask ---------------------------------------------
__global__ void edgemask_kernel(const void* __restrict__ valid_raw,
                                const int* __restrict__ nbr) {
    int e = blockIdx.x * blockDim.x + threadIdx.x;
    if (e >= NNODES * KNBR) return;
    int mode = g_valid_mode;
    bool valid;
    if (mode == 1)      valid = ((const unsigned char*)valid_raw)[e] != 0;
    else if (mode == 2) valid = ((const float*)valid_raw)[e] != 0.0f;
    else                valid = ((const int*)valid_raw)[e] != 0;
    bool masked = (!valid) || (g_rowsum[nbr[e]] == 0.0f);
    g_mask[e] = masked ? 1 : 0;
}

// ---------------- activation helpers ----------------------------------------
template <int ACT>
__device__ __forceinline__ float act_fn(float x) {
    if constexpr (ACT == 1) return fmaxf(x, 0.0f);
    else if constexpr (ACT == 2) return tanhf(x);
    else return x;
}

// ---------------- tiled fp32 GEMM: C[M,ND] = act(A[M,KD] @ W[KD,ND] + bias) --
// BM=64 rows/block, 256 threads. W and the A tile are fully smem-resident
// (single K tile, loaded once). Thread (rowg, colg) computes an 8 x TN
// microtile; A reads are warp-uniform broadcasts, W reads are vectorized.
template <int KD, int ND, int ACT>
__global__ __launch_bounds__(256)
void gemm_kernel(const float* __restrict__ A, const float* __restrict__ W,
                 const float* __restrict__ bias, float* __restrict__ C, int M) {
    constexpr int BM = 64;
    constexpr int TN = ND / 32;
    extern __shared__ float smem[];
    float* As = smem;            // BM*KD
    float* Ws = smem + BM * KD;  // KD*ND

    int tid = threadIdx.x;
    int block0 = blockIdx.x * BM;

    // Load weights (contiguous copy)
    const float4* W4 = (const float4*)W;
    float4* Ws4 = (float4*)Ws;
    #pragma unroll 4
    for (int i = tid; i < KD * ND / 4; i += 256) Ws4[i] = W4[i];

    // Load A tile (rows beyond M zero-filled)
    float4* As4 = (float4*)As;
    #pragma unroll 2
    for (int i = tid; i < BM * KD / 4; i += 256) {
        int r = i / (KD / 4);
        int grow = block0 + r;
        float4 v = make_float4(0.f, 0.f, 0.f, 0.f);
        if (grow < M) v = ((const float4*)A)[(size_t)grow * (KD / 4) + (i % (KD / 4))];
        As4[i] = v;
    }
    __syncthreads();

    int rowg = tid >> 5;
    int colg = tid & 31;

    float acc[8][TN];
    #pragma unroll
    for (int i = 0; i < 8; ++i)
        #pragma unroll
        for (int j = 0; j < TN; ++j) acc[i][j] = 0.0f;

    #pragma unroll 4
    for (int k = 0; k < KD; ++k) {
        float a[8];
        #pragma unroll
        for (int i = 0; i < 8; ++i) a[i] = As[(rowg * 8 + i) * KD + k];
        float b[TN];
        const float* wr = &Ws[k * ND + colg * TN];
        if constexpr (TN == 2) {
            float2 t = *(const float2*)wr;
            b[0] = t.x; b[1] = t.y;
        } else {
            #pragma unroll
            for (int j = 0; j < TN; j += 4) {
                float4 t = *(const float4*)(wr + j);
                b[j] = t.x; b[j + 1] = t.y; b[j + 2] = t.z; b[j + 3] = t.w;
            }
        }
        #pragma unroll
        for (int i = 0; i < 8; ++i)
            #pragma unroll
            for (int j = 0; j < TN; ++j) acc[i][j] = fmaf(a[i], b[j], acc[i][j]);
    }

    // Epilogue
    float bv[TN];
    #pragma unroll
    for (int j = 0; j < TN; ++j) bv[j] = bias ? bias[colg * TN + j] : 0.0f;

    #pragma unroll
    for (int i = 0; i < 8; ++i) {
        int row = block0 + rowg * 8 + i;
        if (row >= M) continue;
        float* cp = C + (size_t)row * ND + colg * TN;
        if constexpr (TN == 2) {
            float2 o;
            o.x = act_fn<ACT>(acc[i][0] + bv[0]);
            o.y = act_fn<ACT>(acc[i][1] + bv[1]);
            *(float2*)cp = o;
        } else {
            #pragma unroll
            for (int j = 0; j < TN; j += 4) {
                float4 o;
                o.x = act_fn<ACT>(acc[i][j + 0] + bv[j + 0]);
                o.y = act_fn<ACT>(acc[i][j + 1] + bv[j + 1]);
                o.z = act_fn<ACT>(acc[i][j + 2] + bv[j + 2]);
                o.w = act_fn<ACT>(acc[i][j + 3] + bv[j + 3]);
                *(float4*)(cp + j) = o;
            }
        }
    }
}

// ---------------- attention: warp per node ----------------------------------
// Q row: lane l owns dims [4l, 4l+4) (head = l/4, dh=16). Head-local dot via
// 4-lane butterfly; softmax over K=5 in registers; gather-weighted V sum.
__global__ __launch_bounds__(256)
void attn_kernel(const float* __restrict__ Q, const float* __restrict__ Kp,
                 const float* __restrict__ Vp, const int* __restrict__ nbr,
                 float* __restrict__ O) {
    int node = blockIdx.x * 8 + (threadIdx.x >> 5);
    if (node >= NNODES) return;
    int lane = threadIdx.x & 31;

    float4 q = ((const float4*)(Q + (size_t)node * DMODEL))[lane];

    int nidx[KNBR];
    float s[KNBR];
    #pragma unroll
    for (int j = 0; j < KNBR; ++j) {
        int n = nbr[node * KNBR + j];
        nidx[j] = n;
        bool masked = g_mask[node * KNBR + j] != 0;
        float4 kk = ((const float4*)(Kp + (size_t)n * DMODEL))[lane];
        float d = q.x * kk.x + q.y * kk.y + q.z * kk.z + q.w * kk.w;
        d += __shfl_xor_sync(0xffffffffu, d, 1);
        d += __shfl_xor_sync(0xffffffffu, d, 2);   // 4-lane (one head) reduce
        s[j] = masked ? -1e30f : d * 0.25f;        // dh^-0.5 = 1/sqrt(16)
    }

    float m = s[0];
    #pragma unroll
    for (int j = 1; j < KNBR; ++j) m = fmaxf(m, s[j]);
    float sum = 0.0f;
    #pragma unroll
    for (int j = 0; j < KNBR; ++j) { s[j] = expf(s[j] - m); sum += s[j]; }
    float inv = 1.0f / sum;

    float4 acc = make_float4(0.f, 0.f, 0.f, 0.f);
    #pragma unroll
    for (int j = 0; j < KNBR; ++j) {
        float p = s[j] * inv;
        float4 v = ((const float4*)(Vp + (size_t)nidx[j] * DMODEL))[lane];
        acc.x = fmaf(p, v.x, acc.x);
        acc.y = fmaf(p, v.y, acc.y);
        acc.z = fmaf(p, v.z, acc.z);
        acc.w = fmaf(p, v.w, acc.w);
    }
    ((float4*)(O + (size_t)node * DMODEL))[lane] = acc;
}

// ---------------- residual + layernorm: warp per row -------------------------
__global__ __launch_bounds__(256)
void ln_kernel(const float* __restrict__ A, const float* __restrict__ B,
               const float* __restrict__ g, const float* __restrict__ be,
               float* __restrict__ Y) {
    int row = blockIdx.x * 8 + (threadIdx.x >> 5);
    if (row >= NNODES) return;
    int lane = threadIdx.x & 31;
    size_t base = (size_t)row * DMODEL;

    float4 a = ((const float4*)(A + base))[lane];
    float4 b = ((const float4*)(B + base))[lane];
    float4 x = make_float4(a.x + b.x, a.y + b.y, a.z + b.z, a.w + b.w);

    float s = x.x + x.y + x.z + x.w;
    #pragma unroll
    for (int o = 16; o > 0; o >>= 1) s += __shfl_xor_sync(0xffffffffu, s, o);
    float mean = s * (1.0f / DMODEL);

    float4 d = make_float4(x.x - mean, x.y - mean, x.z - mean, x.w - mean);
    float v = d.x * d.x + d.y * d.y + d.z * d.z + d.w * d.w;
    #pragma unroll
    for (int o = 16; o > 0; o >>= 1) v += __shfl_xor_sync(0xffffffffu, v, o);
    float var = v * (1.0f / DMODEL);
    float r = rsqrtf(var + 1e-5f);

    float4 gg = ((const float4*)g)[lane];
    float4 bb = ((const float4*)be)[lane];
    float4 y;
    y.x = fmaf(d.x * r, gg.x, bb.x);
    y.y = fmaf(d.y * r, gg.y, bb.y);
    y.z = fmaf(d.z * r, gg.z, bb.z);
    y.w = fmaf(d.w * r, gg.w, bb.w);
    ((float4*)(Y + base))[lane] = y;
}

// ---------------- launch ------------------------------------------------------
extern "C" void kernel_launch(void* const* d_in, const int* in_sizes, int n_in,
                              void* d_out, int out_size) {
    const float* feat = (const float*)d_in[0];
    const int*   nbr  = (const int*)d_in[1];
    const void*  valid = d_in[2];
    const float* wq1 = (const float*)d_in[3];
    const float* wk1 = (const float*)d_in[4];
    const float* wv1 = (const float*)d_in[5];
    const float* wo1 = (const float*)d_in[6];
    const float* bo1 = (const float*)d_in[7];
    const float* w1a = (const float*)d_in[8];
    const float* b1a = (const float*)d_in[9];
    const float* w1b = (const float*)d_in[10];
    const float* b1b = (const float*)d_in[11];
    const float* g1a = (const float*)d_in[12];
    const float* be1a = (const float*)d_in[13];
    const float* g1b = (const float*)d_in[14];
    const float* be1b = (const float*)d_in[15];
    const float* wq2 = (const float*)d_in[16];
    const float* wk2 = (const float*)d_in[17];
    const float* wv2 = (const float*)d_in[18];
    const float* wo2 = (const float*)d_in[19];
    const float* bo2 = (const float*)d_in[20];
    const float* w2a = (const float*)d_in[21];
    const float* b2a = (const float*)d_in[22];
    const float* w2b = (const float*)d_in[23];
    const float* b2b = (const float*)d_in[24];
    const float* g2a = (const float*)d_in[25];
    const float* be2a = (const float*)d_in[26];
    const float* g2b = (const float*)d_in[27];
    const float* be2b = (const float*)d_in[28];
    const float* w4 = (const float*)d_in[29];
    const float* b4 = (const float*)d_in[30];

    // Opt-in smem sizes per GEMM instantiation (host-side, capture-safe)
    cudaFuncSetAttribute(gemm_kernel<128, 128, 0>,
                         cudaFuncAttributeMaxDynamicSharedMemorySize, 98304);
    cudaFuncSetAttribute(gemm_kernel<128, 256, 1>,
                         cudaFuncAttributeMaxDynamicSharedMemorySize, 163840);
    cudaFuncSetAttribute(gemm_kernel<256, 128, 0>,
                         cudaFuncAttributeMaxDynamicSharedMemorySize, 196608);
    cudaFuncSetAttribute(gemm_kernel<128, 64, 2>,
                         cudaFuncAttributeMaxDynamicSharedMemorySize, 65536);

    float *pQ, *pK, *pV, *pO, *pT, *pX1, *pX2, *pH;
    cudaGetSymbolAddress((void**)&pQ, g_Q);
    cudaGetSymbolAddress((void**)&pK, g_K);
    cudaGetSymbolAddress((void**)&pV, g_V);
    cudaGetSymbolAddress((void**)&pO, g_O);
    cudaGetSymbolAddress((void**)&pT, g_T);
    cudaGetSymbolAddress((void**)&pX1, g_X1);
    cudaGetSymbolAddress((void**)&pX2, g_X2);
    cudaGetSymbolAddress((void**)&pH, g_H);

    const int M = NNODES;
    const int GB = (M + 63) / 64;        // gemm blocks
    const int GW = (M + 7) / 8;          // warp-per-row blocks
    const int GE = (M * KNBR + 255) / 256;

    detect_valid_kernel<<<1, 1>>>((const unsigned int*)valid);
    rowsum_kernel<<<GW, 256>>>(feat);
    edgemask_kernel<<<GE, 256>>>(valid, nbr);

    // ---- layer 1 (q stream = feat) ----
    gemm_kernel<128, 128, 0><<<GB, 256, 98304>>>(feat, wq1, nullptr, pQ, M);
    gemm_kernel<128, 128, 0><<<GB, 256, 98304>>>(feat, wk1, nullptr, pK, M);
    gemm_kernel<128, 128, 0><<<GB, 256, 98304>>>(feat, wv1, nullptr, pV, M);
    attn_kernel<<<GW, 256>>>(pQ, pK, pV, nbr, pO);
    gemm_kernel<128, 128, 0><<<GB, 256, 98304>>>(pO, wo1, bo1, pT, M);
    ln_kernel<<<GW, 256>>>(feat, pT, g1a, be1a, pX1);
    gemm_kernel<128, 256, 1><<<GB, 256, 163840>>>(pX1, w1a, b1a, pH, M);
    gemm_kernel<256, 128, 0><<<GB, 256, 196608>>>(pH, w1b, b1b, pT, M);
    ln_kernel<<<GW, 256>>>(pX1, pT, g1b, be1b, pX2);

    // ---- layer 2 (q stream = pX2, k/v still from feat) ----
    gemm_kernel<128, 128, 0><<<GB, 256, 98304>>>(pX2, wq2, nullptr, pQ, M);
    gemm_kernel<128, 128, 0><<<GB, 256, 98304>>>(feat, wk2, nullptr, pK, M);
    gemm_kernel<128, 128, 0><<<GB, 256, 98304>>>(feat, wv2, nullptr, pV, M);
    attn_kernel<<<GW, 256>>>(pQ, pK, pV, nbr, pO);
    gemm_kernel<128, 128, 0><<<GB, 256, 98304>>>(pO, wo2, bo2, pT, M);
    ln_kernel<<<GW, 256>>>(pX2, pT, g2a, be2a, pX1);
    gemm_kernel<128, 256, 1><<<GB, 256, 163840>>>(pX1, w2a, b2a, pH, M);
    gemm_kernel<256, 128, 0><<<GB, 256, 196608>>>(pH, w2b, b2b, pT, M);
    ln_kernel<<<GW, 256>>>(pX1, pT, g2b, be2b, pX2);

    // ---- final head ----
    gemm_kernel<128, 64, 2><<<GB, 256, 65536>>>(pX2, w4, b4, (float*)d_out, M);
}

// round 7
// speedup vs baseline: 1.9420x; 1.9420x over previous
#include <cuda_runtime.h>
#include <math.h>

#define NNODES 300000
#define DMODEL 128
#define KNBR 5

// ---------------- scratch (device globals; no runtime allocation) ----------
__device__ float g_rowsum[NNODES];
__device__ unsigned char g_mask[NNODES * KNBR];
__device__ int g_valid_mode;   // 0 = int32 bools, 1 = uint8 bools, 2 = float bools
__device__ float g_Q[NNODES * DMODEL];
__device__ float g_K[NNODES * DMODEL];
__device__ float g_V[NNODES * DMODEL];
__device__ float g_O[NNODES * DMODEL];
__device__ float g_X1[NNODES * DMODEL];
__device__ float g_X2[NNODES * DMODEL];
__device__ float g_H[NNODES * 2 * DMODEL];

// ---------------- nbr_valid encoding detection -----------------------------
__global__ void detect_valid_kernel(const unsigned int* v) {
    int all01 = 1, allf = 1;
    for (int t = 0; t < 2048; ++t) {
        unsigned int x = v[t];
        if (x > 1u) all01 = 0;
        if (x != 0u && x != 0x3f800000u) allf = 0;
    }
    g_valid_mode = all01 ? 0 : (allf ? 2 : 1);
}

// ---------------- per-row feat sum (for the ==0 mask) -----------------------
__global__ void rowsum_kernel(const float* __restrict__ feat) {
    int row = blockIdx.x * 8 + (threadIdx.x >> 5);
    if (row >= NNODES) return;
    int lane = threadIdx.x & 31;
    float4 v = ((const float4*)(feat + (size_t)row * DMODEL))[lane];
    float s = v.x + v.y + v.z + v.w;
    #pragma unroll
    for (int o = 16; o > 0; o >>= 1) s += __shfl_xor_sync(0xffffffffu, s, o);
    if (lane == 0) g_rowsum[row] = s;
}

// ---------------- per-edge mask ---------------------------------------------
__global__ void edgemask_kernel(const void* __restrict__ valid_raw,
                                const int* __restrict__ nbr) {
    int e = blockIdx.x * blockDim.x + threadIdx.x;
    if (e >= NNODES * KNBR) return;
    int mode = g_valid_mode;
    bool valid;
    if (mode == 1)      valid = ((const unsigned char*)valid_raw)[e] != 0;
    else if (mode == 2) valid = ((const float*)valid_raw)[e] != 0.0f;
    else                valid = ((const int*)valid_raw)[e] != 0;
    bool masked = (!valid) || (g_rowsum[nbr[e]] == 0.0f);
    g_mask[e] = masked ? 1 : 0;
}

// ============================================================================
// Tensor-core tf32 GEMM machinery
//   Block tile: BM=64 rows x BN=128 cols, K staged in 128-chunks in smem.
//   256 threads = 8 warps (2x4), warp tile 32x32 -> mma m16n8k8: 2x4 tiles.
//   smem: As 64x132 + Ws 128x132 (padded stride kills bank conflicts).
// ============================================================================
#define LDS 132
#define SMEM_BYTES ((64 * LDS + 128 * LDS) * 4)

__device__ __forceinline__ float tf32r(float x) {
    unsigned r;
    asm("cvt.rna.tf32.f32 %0, %1;" : "=r"(r) : "f"(x));
    return __uint_as_float(r);
}

__device__ __forceinline__ void mma8(float* c, unsigned a0, unsigned a1,
                                     unsigned a2, unsigned a3,
                                     unsigned b0, unsigned b1) {
    asm volatile(
        "mma.sync.aligned.m16n8k8.row.col.f32.tf32.tf32.f32 "
        "{%0,%1,%2,%3}, {%4,%5,%6,%7}, {%8,%9}, {%0,%1,%2,%3};\n"
        : "+f"(c[0]), "+f"(c[1]), "+f"(c[2]), "+f"(c[3])
        : "r"(a0), "r"(a1), "r"(a2), "r"(a3), "r"(b0), "r"(b1));
}

// Load one 64x128 A chunk (rows m0.., k cols kc0..kc0+128) into As (tf32).
__device__ __forceinline__ void load_A(float* As, const float* A, int m0,
                                       int kc0, int KD, int M, int tid) {
    #pragma unroll 4
    for (int i = tid; i < 64 * 32; i += 256) {
        int r = i >> 5, c4 = (i & 31) * 4;
        int grow = m0 + r;
        float4 v = make_float4(0.f, 0.f, 0.f, 0.f);
        if (grow < M)
            v = *(const float4*)(A + (size_t)grow * KD + kc0 + c4);
        float* d = As + r * LDS + c4;
        d[0] = tf32r(v.x); d[1] = tf32r(v.y); d[2] = tf32r(v.z); d[3] = tf32r(v.w);
    }
}

// Load one 128x128 W chunk (k rows kc0.., cols n0..n0+128) into Ws (tf32).
__device__ __forceinline__ void load_W(float* Ws, const float* W, int kc0,
                                       int n0, int ND, int tid) {
    #pragma unroll 4
    for (int i = tid; i < 128 * 32; i += 256) {
        int kr = i >> 5, c4 = (i & 31) * 4;
        int gc = n0 + c4;
        float4 v = make_float4(0.f, 0.f, 0.f, 0.f);
        if (gc < ND)
            v = *(const float4*)(W + (size_t)(kc0 + kr) * ND + gc);
        float* d = Ws + kr * LDS + c4;
        d[0] = tf32r(v.x); d[1] = tf32r(v.y); d[2] = tf32r(v.z); d[3] = tf32r(v.w);
    }
}

// One 128-deep K chunk of MMAs into acc[2][4][4].
__device__ __forceinline__ void mma_chunk(float (&acc)[2][4][4],
                                          const float* As, const float* Ws,
                                          int lane, int wm, int wn) {
    int tr = lane >> 2, tc = lane & 3;
    #pragma unroll
    for (int k = 0; k < 128; k += 8) {
        unsigned a[2][4];
        #pragma unroll
        for (int mt = 0; mt < 2; ++mt) {
            const float* p = As + (wm * 32 + mt * 16 + tr) * LDS + k + tc;
            a[mt][0] = __float_as_uint(p[0]);
            a[mt][1] = __float_as_uint(p[8 * LDS]);
            a[mt][2] = __float_as_uint(p[4]);
            a[mt][3] = __float_as_uint(p[8 * LDS + 4]);
        }
        #pragma unroll
        for (int nt = 0; nt < 4; ++nt) {
            int cb = wn * 32 + nt * 8 + tr;
            unsigned b0 = __float_as_uint(Ws[(k + tc) * LDS + cb]);
            unsigned b1 = __float_as_uint(Ws[(k + 4 + tc) * LDS + cb]);
            #pragma unroll
            for (int mt = 0; mt < 2; ++mt)
                mma8(acc[mt][nt], a[mt][0], a[mt][1], a[mt][2], a[mt][3], b0, b1);
        }
    }
}

// ---------------- fused multi-output GEMM (QKV): C_j = A @ W_j, KD=128 ------
__global__ __launch_bounds__(256, 2)
void gemm3_kernel(const float* __restrict__ A,
                  const float* __restrict__ W0, const float* __restrict__ W1,
                  const float* __restrict__ W2,
                  float* __restrict__ C0, float* __restrict__ C1,
                  float* __restrict__ C2, int M) {
    extern __shared__ float smem[];
    float* As = smem;
    float* Ws = smem + 64 * LDS;
    int tid = threadIdx.x;
    int lane = tid & 31, wid = tid >> 5, wm = wid >> 2, wn = wid & 3;
    int m0 = blockIdx.x * 64;

    load_A(As, A, m0, 0, 128, M, tid);

    const float* Wl[3] = {W0, W1, W2};
    float* Cl[3] = {C0, C1, C2};
    #pragma unroll
    for (int j = 0; j < 3; ++j) {
        if (Wl[j] == nullptr) break;
        if (j > 0) __syncthreads();
        load_W(Ws, Wl[j], 0, 0, 128, tid);
        __syncthreads();

        float acc[2][4][4];
        #pragma unroll
        for (int mt = 0; mt < 2; ++mt)
            #pragma unroll
            for (int nt = 0; nt < 4; ++nt)
                #pragma unroll
                for (int q = 0; q < 4; ++q) acc[mt][nt][q] = 0.f;

        mma_chunk(acc, As, Ws, lane, wm, wn);

        float* C = Cl[j];
        #pragma unroll
        for (int mt = 0; mt < 2; ++mt) {
            int r0 = m0 + wm * 32 + mt * 16 + (lane >> 2);
            #pragma unroll
            for (int nt = 0; nt < 4; ++nt) {
                int col = wn * 32 + nt * 8 + (lane & 3) * 2;
                if (r0 < M)
                    *(float2*)(C + (size_t)r0 * 128 + col) =
                        make_float2(acc[mt][nt][0], acc[mt][nt][1]);
                if (r0 + 8 < M)
                    *(float2*)(C + (size_t)(r0 + 8) * 128 + col) =
                        make_float2(acc[mt][nt][2], acc[mt][nt][3]);
            }
        }
    }
}

// ---------------- GEMM + bias + residual + LayerNorm fused ------------------
// Y = LN(R + A@W + bias) * g + be.  ND = 128 (full row in block).
template <int KD>
__global__ __launch_bounds__(256, 2)
void gemm_ln_kernel(const float* __restrict__ A, const float* __restrict__ W,
                    const float* __restrict__ bias, const float* __restrict__ R,
                    const float* __restrict__ g, const float* __restrict__ be,
                    float* __restrict__ Y, int M) {
    extern __shared__ float smem[];
    float* As = smem;
    float* Ws = smem + 64 * LDS;
    int tid = threadIdx.x;
    int lane = tid & 31, wid = tid >> 5, wm = wid >> 2, wn = wid & 3;
    int m0 = blockIdx.x * 64;

    float acc[2][4][4];
    #pragma unroll
    for (int mt = 0; mt < 2; ++mt)
        #pragma unroll
        for (int nt = 0; nt < 4; ++nt)
            #pragma unroll
            for (int q = 0; q < 4; ++q) acc[mt][nt][q] = 0.f;

    #pragma unroll
    for (int kc = 0; kc < KD / 128; ++kc) {
        if (kc > 0) __syncthreads();
        load_A(As, A, m0, kc * 128, KD, M, tid);
        load_W(Ws, W, kc * 128, 0, 128, tid);
        __syncthreads();
        mma_chunk(acc, As, Ws, lane, wm, wn);
    }
    __syncthreads();

    // Stage pre-LN values into smem (reuse As region: 64 x LDS)
    float* Xs = As;
    #pragma unroll
    for (int mt = 0; mt < 2; ++mt) {
        int r0 = wm * 32 + mt * 16 + (lane >> 2);
        #pragma unroll
        for (int nt = 0; nt < 4; ++nt) {
            int col = wn * 32 + nt * 8 + (lane & 3) * 2;
            *(float2*)(Xs + r0 * LDS + col) = make_float2(acc[mt][nt][0], acc[mt][nt][1]);
            *(float2*)(Xs + (r0 + 8) * LDS + col) = make_float2(acc[mt][nt][2], acc[mt][nt][3]);
        }
    }
    __syncthreads();

    // LayerNorm: warp per row (8 rows per warp), lane owns 4 cols.
    int col0 = lane * 4;
    float4 bb4 = *(const float4*)(bias + col0);
    float4 gg = *(const float4*)(g + col0);
    float4 ee = *(const float4*)(be + col0);
    #pragma unroll
    for (int rr = 0; rr < 8; ++rr) {
        int rl = wid * 8 + rr;
        int grow = m0 + rl;
        if (grow >= M) break;
        float4 rv = *(const float4*)(R + (size_t)grow * 128 + col0);
        float x0 = Xs[rl * LDS + col0 + 0] + bb4.x + rv.x;
        float x1 = Xs[rl * LDS + col0 + 1] + bb4.y + rv.y;
        float x2 = Xs[rl * LDS + col0 + 2] + bb4.z + rv.z;
        float x3 = Xs[rl * LDS + col0 + 3] + bb4.w + rv.w;
        float s = x0 + x1 + x2 + x3;
        #pragma unroll
        for (int o = 16; o > 0; o >>= 1) s += __shfl_xor_sync(0xffffffffu, s, o);
        float mean = s * (1.0f / 128.0f);
        float d0 = x0 - mean, d1 = x1 - mean, d2 = x2 - mean, d3 = x3 - mean;
        float v = d0 * d0 + d1 * d1 + d2 * d2 + d3 * d3;
        #pragma unroll
        for (int o = 16; o > 0; o >>= 1) v += __shfl_xor_sync(0xffffffffu, v, o);
        float rs = rsqrtf(v * (1.0f / 128.0f) + 1e-5f);
        float4 y;
        y.x = fmaf(d0 * rs, gg.x, ee.x);
        y.y = fmaf(d1 * rs, gg.y, ee.y);
        y.z = fmaf(d2 * rs, gg.z, ee.z);
        y.w = fmaf(d3 * rs, gg.w, ee.w);
        *(float4*)(Y + (size_t)grow * 128 + col0) = y;
    }
}

// ---------------- GEMM + bias + activation (relu / tanh / none) -------------
// C[M,ND] = act(A[M,KD] @ W[KD,ND] + bias).  n-chunked by gridDim.y.
template <int ACT>
__global__ __launch_bounds__(256, 2)
void gemm_act_kernel(const float* __restrict__ A, const float* __restrict__ W,
                     const float* __restrict__ bias, float* __restrict__ C,
                     int M, int KD, int ND) {
    extern __shared__ float smem[];
    float* As = smem;
    float* Ws = smem + 64 * LDS;
    int tid = threadIdx.x;
    int lane = tid & 31, wid = tid >> 5, wm = wid >> 2, wn = wid & 3;
    int m0 = blockIdx.x * 64;
    int n0 = blockIdx.y * 128;

    float acc[2][4][4];
    #pragma unroll
    for (int mt = 0; mt < 2; ++mt)
        #pragma unroll
        for (int nt = 0; nt < 4; ++nt)
            #pragma unroll
            for (int q = 0; q < 4; ++q) acc[mt][nt][q] = 0.f;

    for (int kc = 0; kc < KD / 128; ++kc) {
        if (kc > 0) __syncthreads();
        load_A(As, A, m0, kc * 128, KD, M, tid);
        load_W(Ws, W, kc * 128, n0, ND, tid);
        __syncthreads();
        mma_chunk(acc, As, Ws, lane, wm, wn);
    }

    #pragma unroll
    for (int mt = 0; mt < 2; ++mt) {
        int r0 = m0 + wm * 32 + mt * 16 + (lane >> 2);
        #pragma unroll
        for (int nt = 0; nt < 4; ++nt) {
            int col = n0 + wn * 32 + nt * 8 + (lane & 3) * 2;
            if (col >= ND) continue;
            float b0 = bias ? bias[col] : 0.f;
            float b1 = bias ? bias[col + 1] : 0.f;
            float v0 = acc[mt][nt][0] + b0, v1 = acc[mt][nt][1] + b1;
            float v2 = acc[mt][nt][2] + b0, v3 = acc[mt][nt][3] + b1;
            if (ACT == 1) {
                v0 = fmaxf(v0, 0.f); v1 = fmaxf(v1, 0.f);
                v2 = fmaxf(v2, 0.f); v3 = fmaxf(v3, 0.f);
            } else if (ACT == 2) {
                v0 = tanhf(v0); v1 = tanhf(v1); v2 = tanhf(v2); v3 = tanhf(v3);
            }
            if (r0 < M)
                *(float2*)(C + (size_t)r0 * ND + col) = make_float2(v0, v1);
            if (r0 + 8 < M)
                *(float2*)(C + (size_t)(r0 + 8) * ND + col) = make_float2(v2, v3);
        }
    }
}

// ---------------- attention: warp per node ----------------------------------
__global__ __launch_bounds__(256)
void attn_kernel(const float* __restrict__ Q, const float* __restrict__ Kp,
                 const float* __restrict__ Vp, const int* __restrict__ nbr,
                 float* __restrict__ O) {
    int node = blockIdx.x * 8 + (threadIdx.x >> 5);
    if (node >= NNODES) return;
    int lane = threadIdx.x & 31;

    float4 q = ((const float4*)(Q + (size_t)node * DMODEL))[lane];

    int nidx[KNBR];
    float s[KNBR];
    #pragma unroll
    for (int j = 0; j < KNBR; ++j) {
        int n = nbr[node * KNBR + j];
        nidx[j] = n;
        bool masked = g_mask[node * KNBR + j] != 0;
        float4 kk = ((const float4*)(Kp + (size_t)n * DMODEL))[lane];
        float d = q.x * kk.x + q.y * kk.y + q.z * kk.z + q.w * kk.w;
        d += __shfl_xor_sync(0xffffffffu, d, 1);
        d += __shfl_xor_sync(0xffffffffu, d, 2);   // 4-lane (one head) reduce
        s[j] = masked ? -1e30f : d * 0.25f;        // dh^-0.5 = 1/sqrt(16)
    }

    float m = s[0];
    #pragma unroll
    for (int j = 1; j < KNBR; ++j) m = fmaxf(m, s[j]);
    float sum = 0.0f;
    #pragma unroll
    for (int j = 0; j < KNBR; ++j) { s[j] = expf(s[j] - m); sum += s[j]; }
    float inv = 1.0f / sum;

    float4 acc = make_float4(0.f, 0.f, 0.f, 0.f);
    #pragma unroll
    for (int j = 0; j < KNBR; ++j) {
        float p = s[j] * inv;
        float4 v = ((const float4*)(Vp + (size_t)nidx[j] * DMODEL))[lane];
        acc.x = fmaf(p, v.x, acc.x);
        acc.y = fmaf(p, v.y, acc.y);
        acc.z = fmaf(p, v.z, acc.z);
        acc.w = fmaf(p, v.w, acc.w);
    }
    ((float4*)(O + (size_t)node * DMODEL))[lane] = acc;
}

// ---------------- launch ------------------------------------------------------
extern "C" void kernel_launch(void* const* d_in, const int* in_sizes, int n_in,
                              void* d_out, int out_size) {
    const float* feat = (const float*)d_in[0];
    const int*   nbr  = (const int*)d_in[1];
    const void*  valid = d_in[2];
    const float* wq1 = (const float*)d_in[3];
    const float* wk1 = (const float*)d_in[4];
    const float* wv1 = (const float*)d_in[5];
    const float* wo1 = (const float*)d_in[6];
    const float* bo1 = (const float*)d_in[7];
    const float* w1a = (const float*)d_in[8];
    const float* b1a = (const float*)d_in[9];
    const float* w1b = (const float*)d_in[10];
    const float* b1b = (const float*)d_in[11];
    const float* g1a = (const float*)d_in[12];
    const float* be1a = (const float*)d_in[13];
    const float* g1b = (const float*)d_in[14];
    const float* be1b = (const float*)d_in[15];
    const float* wq2 = (const float*)d_in[16];
    const float* wk2 = (const float*)d_in[17];
    const float* wv2 = (const float*)d_in[18];
    const float* wo2 = (const float*)d_in[19];
    const float* bo2 = (const float*)d_in[20];
    const float* w2a = (const float*)d_in[21];
    const float* b2a = (const float*)d_in[22];
    const float* w2b = (const float*)d_in[23];
    const float* b2b = (const float*)d_in[24];
    const float* g2a = (const float*)d_in[25];
    const float* be2a = (const float*)d_in[26];
    const float* g2b = (const float*)d_in[27];
    const float* be2b = (const float*)d_in[28];
    const float* w4 = (const float*)d_in[29];
    const float* b4 = (const float*)d_in[30];

    cudaFuncSetAttribute(gemm3_kernel,
                         cudaFuncAttributeMaxDynamicSharedMemorySize, SMEM_BYTES);
    cudaFuncSetAttribute(gemm_ln_kernel<128>,
                         cudaFuncAttributeMaxDynamicSharedMemorySize, SMEM_BYTES);
    cudaFuncSetAttribute(gemm_ln_kernel<256>,
                         cudaFuncAttributeMaxDynamicSharedMemorySize, SMEM_BYTES);
    cudaFuncSetAttribute(gemm_act_kernel<1>,
                         cudaFuncAttributeMaxDynamicSharedMemorySize, SMEM_BYTES);
    cudaFuncSetAttribute(gemm_act_kernel<2>,
                         cudaFuncAttributeMaxDynamicSharedMemorySize, SMEM_BYTES);

    float *pQ, *pK, *pV, *pO, *pX1, *pX2, *pH;
    cudaGetSymbolAddress((void**)&pQ, g_Q);
    cudaGetSymbolAddress((void**)&pK, g_K);
    cudaGetSymbolAddress((void**)&pV, g_V);
    cudaGetSymbolAddress((void**)&pO, g_O);
    cudaGetSymbolAddress((void**)&pX1, g_X1);
    cudaGetSymbolAddress((void**)&pX2, g_X2);
    cudaGetSymbolAddress((void**)&pH, g_H);

    const int M = NNODES;
    const int GB = (M + 63) / 64;        // tensor-core gemm blocks (BM=64)
    const int GW = (M + 7) / 8;          // warp-per-row blocks
    const int GE = (M * KNBR + 255) / 256;

    detect_valid_kernel<<<1, 1>>>((const unsigned int*)valid);
    rowsum_kernel<<<GW, 256>>>(feat);
    edgemask_kernel<<<GE, 256>>>(valid, nbr);

    // ---- layer 1 ----
    gemm3_kernel<<<GB, 256, SMEM_BYTES>>>(feat, wq1, wk1, wv1, pQ, pK, pV, M);
    attn_kernel<<<GW, 256>>>(pQ, pK, pV, nbr, pO);
    gemm_ln_kernel<128><<<GB, 256, SMEM_BYTES>>>(pO, wo1, bo1, feat, g1a, be1a, pX1, M);
    gemm_act_kernel<1><<<dim3(GB, 2), 256, SMEM_BYTES>>>(pX1, w1a, b1a, pH, M, 128, 256);
    gemm_ln_kernel<256><<<GB, 256, SMEM_BYTES>>>(pH, w1b, b1b, pX1, g1b, be1b, pX2, M);

    // ---- layer 2 (q from pX2; k/v from feat) ----
    gemm3_kernel<<<GB, 256, SMEM_BYTES>>>(pX2, wq2, nullptr, nullptr, pQ, nullptr, nullptr, M);
    gemm3_kernel<<<GB, 256, SMEM_BYTES>>>(feat, wk2, wv2, nullptr, pK, pV, nullptr, M);
    attn_kernel<<<GW, 256>>>(pQ, pK, pV, nbr, pO);
    gemm_ln_kernel<128><<<GB, 256, SMEM_BYTES>>>(pO, wo2, bo2, pX2, g2a, be2a, pX1, M);
    gemm_act_kernel<1><<<dim3(GB, 2), 256, SMEM_BYTES>>>(pX1, w2a, b2a, pH, M, 128, 256);
    gemm_ln_kernel<256><<<GB, 256, SMEM_BYTES>>>(pH, w2b, b2b, pX1, g2b, be2b, pX2, M);

    // ---- final head (tanh, ND=64) ----
    gemm_act_kernel<2><<<dim3(GB, 1), 256, SMEM_BYTES>>>(pX2, w4, b4, (float*)d_out, M, 128, 64);
}

// round 8
// speedup vs baseline: 2.1692x; 1.1170x over previous
#include <cuda_runtime.h>
#include <math.h>

#define NNODES 300000
#define DMODEL 128
#define KNBR 5

// ---------------- scratch (device globals; no runtime allocation) ----------
__device__ float g_rowsum[NNODES];
__device__ unsigned char g_mask[NNODES * KNBR];
__device__ int g_valid_mode;   // 0 = int32 bools, 1 = uint8 bools, 2 = float bools
__device__ float g_Q[NNODES * DMODEL];
__device__ float g_K[NNODES * DMODEL];
__device__ float g_V[NNODES * DMODEL];
__device__ float g_O[NNODES * DMODEL];
__device__ float g_X1[NNODES * DMODEL];
__device__ float g_X2[NNODES * DMODEL];
__device__ float g_H[NNODES * 2 * DMODEL];

// ---------------- nbr_valid encoding detection -----------------------------
__global__ void detect_valid_kernel(const unsigned int* v) {
    int all01 = 1, allf = 1;
    for (int t = 0; t < 2048; ++t) {
        unsigned int x = v[t];
        if (x > 1u) all01 = 0;
        if (x != 0u && x != 0x3f800000u) allf = 0;
    }
    g_valid_mode = all01 ? 0 : (allf ? 2 : 1);
}

// ---------------- per-row feat sum (for the ==0 mask) -----------------------
__global__ void rowsum_kernel(const float* __restrict__ feat) {
    int row = blockIdx.x * 8 + (threadIdx.x >> 5);
    if (row >= NNODES) return;
    int lane = threadIdx.x & 31;
    float4 v = ((const float4*)(feat + (size_t)row * DMODEL))[lane];
    float s = v.x + v.y + v.z + v.w;
    #pragma unroll
    for (int o = 16; o > 0; o >>= 1) s += __shfl_xor_sync(0xffffffffu, s, o);
    if (lane == 0) g_rowsum[row] = s;
}

// ---------------- per-edge mask ---------------------------------------------
__global__ void edgemask_kernel(const void* __restrict__ valid_raw,
                                const int* __restrict__ nbr) {
    int e = blockIdx.x * blockDim.x + threadIdx.x;
    if (e >= NNODES * KNBR) return;
    int mode = g_valid_mode;
    bool valid;
    if (mode == 1)      valid = ((const unsigned char*)valid_raw)[e] != 0;
    else if (mode == 2) valid = ((const float*)valid_raw)[e] != 0.0f;
    else                valid = ((const int*)valid_raw)[e] != 0;
    bool masked = (!valid) || (g_rowsum[nbr[e]] == 0.0f);
    g_mask[e] = masked ? 1 : 0;
}

// ============================================================================
// Tensor-core tf32 GEMM machinery, round-7 edition.
//   Block tile: BM=128 x BN=128, 256 threads = 8 warps (2m x 4n),
//   warp tile 64x32 -> m16n8k8 tiles: mt=4, nt=4 (16 mmas / warp-k-step).
//   A staged fully (128 x 128 cols, stride 132, conflict-free: 4*tr+tc),
//   W staged in 64-deep k-chunks (stride 136, conflict-free: 8*tc+tr).
//   smem/CTA = (128*132 + 64*136)*4 = 102400 B -> 2 CTAs/SM.
// ============================================================================
#define LDSA 132
#define LDSB 136
#define SMEM_FLOATS (128 * LDSA + 64 * LDSB)
#define SMEM_BYTES (SMEM_FLOATS * 4)

__device__ __forceinline__ float tf32r(float x) {
    unsigned r;
    asm("cvt.rna.tf32.f32 %0, %1;" : "=r"(r) : "f"(x));
    return __uint_as_float(r);
}

__device__ __forceinline__ void mma8(float* c, unsigned a0, unsigned a1,
                                     unsigned a2, unsigned a3,
                                     unsigned b0, unsigned b1) {
    asm volatile(
        "mma.sync.aligned.m16n8k8.row.col.f32.tf32.tf32.f32 "
        "{%0,%1,%2,%3}, {%4,%5,%6,%7}, {%8,%9}, {%0,%1,%2,%3};\n"
        : "+f"(c[0]), "+f"(c[1]), "+f"(c[2]), "+f"(c[3])
        : "r"(a0), "r"(a1), "r"(a2), "r"(a3), "r"(b0), "r"(b1));
}

// Load a 128-row x 128-col A chunk (k cols kc0..kc0+128) into As (tf32).
__device__ __forceinline__ void load_A128(float* As, const float* A, int m0,
                                          int kc0, int KD, int M, int tid) {
    #pragma unroll 4
    for (int i = tid; i < 128 * 32; i += 256) {
        int r = i >> 5, c4 = (i & 31) * 4;
        int grow = m0 + r;
        float4 v = make_float4(0.f, 0.f, 0.f, 0.f);
        if (grow < M)
            v = *(const float4*)(A + (size_t)grow * KD + kc0 + c4);
        float* d = As + r * LDSA + c4;
        d[0] = tf32r(v.x); d[1] = tf32r(v.y); d[2] = tf32r(v.z); d[3] = tf32r(v.w);
    }
}

// Load a 64-krow x 128-ncol W chunk (k rows kc0.., cols n0..) into Ws (tf32).
__device__ __forceinline__ void load_W64(float* Ws, const float* W, int kc0,
                                         int n0, int ND, int tid) {
    #pragma unroll 4
    for (int i = tid; i < 64 * 32; i += 256) {
        int kr = i >> 5, c4 = (i & 31) * 4;
        int gc = n0 + c4;
        float4 v = make_float4(0.f, 0.f, 0.f, 0.f);
        if (gc < ND)
            v = *(const float4*)(W + (size_t)(kc0 + kr) * ND + gc);
        float* d = Ws + kr * LDSB + c4;
        d[0] = tf32r(v.x); d[1] = tf32r(v.y); d[2] = tf32r(v.z); d[3] = tf32r(v.w);
    }
}

// One 64-deep K chunk of MMAs into acc[4][4][4]. kbase = offset within As cols.
__device__ __forceinline__ void mma64(float (&acc)[4][4][4],
                                      const float* As, const float* Ws,
                                      int kbase, int lane, int wm, int wn) {
    int tr = lane >> 2, tc = lane & 3;
    #pragma unroll
    for (int k = 0; k < 64; k += 8) {
        unsigned a[4][4];
        #pragma unroll
        for (int mt = 0; mt < 4; ++mt) {
            const float* p = As + (wm * 64 + mt * 16 + tr) * LDSA + kbase + k + tc;
            a[mt][0] = __float_as_uint(p[0]);
            a[mt][1] = __float_as_uint(p[8 * LDSA]);
            a[mt][2] = __float_as_uint(p[4]);
            a[mt][3] = __float_as_uint(p[8 * LDSA + 4]);
        }
        #pragma unroll
        for (int nt = 0; nt < 4; ++nt) {
            int cb = wn * 32 + nt * 8 + tr;
            unsigned b0 = __float_as_uint(Ws[(k + tc) * LDSB + cb]);
            unsigned b1 = __float_as_uint(Ws[(k + 4 + tc) * LDSB + cb]);
            #pragma unroll
            for (int mt = 0; mt < 4; ++mt)
                mma8(acc[mt][nt], a[mt][0], a[mt][1], a[mt][2], a[mt][3], b0, b1);
        }
    }
}

__device__ __forceinline__ void zero_acc(float (&acc)[4][4][4]) {
    #pragma unroll
    for (int mt = 0; mt < 4; ++mt)
        #pragma unroll
        for (int nt = 0; nt < 4; ++nt)
            #pragma unroll
            for (int q = 0; q < 4; ++q) acc[mt][nt][q] = 0.f;
}

// ---------------- fused multi-output GEMM (QKV): C_j = A @ W_j, KD=128 ------
__global__ __launch_bounds__(256, 2)
void gemm3_kernel(const float* __restrict__ A,
                  const float* __restrict__ W0, const float* __restrict__ W1,
                  const float* __restrict__ W2,
                  float* __restrict__ C0, float* __restrict__ C1,
                  float* __restrict__ C2, int M) {
    extern __shared__ float smem[];
    float* As = smem;
    float* Ws = smem + 128 * LDSA;
    int tid = threadIdx.x;
    int lane = tid & 31, wid = tid >> 5, wm = wid >> 2, wn = wid & 3;
    int m0 = blockIdx.x * 128;

    load_A128(As, A, m0, 0, 128, M, tid);   // visible after first __syncthreads

    const float* Wl[3] = {W0, W1, W2};
    float* Cl[3] = {C0, C1, C2};
    for (int j = 0; j < 3; ++j) {
        if (Wl[j] == nullptr) break;
        float acc[4][4][4];
        zero_acc(acc);
        #pragma unroll
        for (int kc = 0; kc < 2; ++kc) {
            __syncthreads();                 // prior mma/epilogue done with Ws
            load_W64(Ws, Wl[j], kc * 64, 0, 128, tid);
            __syncthreads();
            mma64(acc, As, Ws, kc * 64, lane, wm, wn);
        }
        float* C = Cl[j];
        #pragma unroll
        for (int mt = 0; mt < 4; ++mt) {
            int r0 = m0 + wm * 64 + mt * 16 + (lane >> 2);
            #pragma unroll
            for (int nt = 0; nt < 4; ++nt) {
                int col = wn * 32 + nt * 8 + (lane & 3) * 2;
                if (r0 < M)
                    *(float2*)(C + (size_t)r0 * 128 + col) =
                        make_float2(acc[mt][nt][0], acc[mt][nt][1]);
                if (r0 + 8 < M)
                    *(float2*)(C + (size_t)(r0 + 8) * 128 + col) =
                        make_float2(acc[mt][nt][2], acc[mt][nt][3]);
            }
        }
    }
}

// ---------------- GEMM + bias + residual + LayerNorm fused ------------------
// Y = LN(R + A@W + bias) * g + be.  ND = 128 (full row in block).
template <int KD>
__global__ __launch_bounds__(256, 2)
void gemm_ln_kernel(const float* __restrict__ A, const float* __restrict__ W,
                    const float* __restrict__ bias, const float* __restrict__ R,
                    const float* __restrict__ g, const float* __restrict__ be,
                    float* __restrict__ Y, int M) {
    extern __shared__ float smem[];
    float* As = smem;
    float* Ws = smem + 128 * LDSA;
    int tid = threadIdx.x;
    int lane = tid & 31, wid = tid >> 5, wm = wid >> 2, wn = wid & 3;
    int m0 = blockIdx.x * 128;

    float acc[4][4][4];
    zero_acc(acc);

    #pragma unroll
    for (int kc128 = 0; kc128 < KD / 128; ++kc128) {
        #pragma unroll
        for (int kc = 0; kc < 2; ++kc) {
            __syncthreads();
            if (kc == 0) load_A128(As, A, m0, kc128 * 128, KD, M, tid);
            load_W64(Ws, W, kc128 * 128 + kc * 64, 0, 128, tid);
            __syncthreads();
            mma64(acc, As, Ws, kc * 64, lane, wm, wn);
        }
    }
    __syncthreads();

    // Stage pre-LN values into smem (reuse As region as 128 x LDSA)
    float* Xs = As;
    #pragma unroll
    for (int mt = 0; mt < 4; ++mt) {
        int r0 = wm * 64 + mt * 16 + (lane >> 2);
        #pragma unroll
        for (int nt = 0; nt < 4; ++nt) {
            int col = wn * 32 + nt * 8 + (lane & 3) * 2;
            *(float2*)(Xs + r0 * LDSA + col) = make_float2(acc[mt][nt][0], acc[mt][nt][1]);
            *(float2*)(Xs + (r0 + 8) * LDSA + col) = make_float2(acc[mt][nt][2], acc[mt][nt][3]);
        }
    }
    __syncthreads();

    // LayerNorm: warp per row, 16 rows per warp, lane owns 4 cols.
    int col0 = lane * 4;
    float4 bb4 = *(const float4*)(bias + col0);
    float4 gg = *(const float4*)(g + col0);
    float4 ee = *(const float4*)(be + col0);
    #pragma unroll
    for (int rr = 0; rr < 16; ++rr) {
        int rl = wid * 16 + rr;
        int grow = m0 + rl;
        if (grow >= M) break;
        float4 rv = *(const float4*)(R + (size_t)grow * 128 + col0);
        float x0 = Xs[rl * LDSA + col0 + 0] + bb4.x + rv.x;
        float x1 = Xs[rl * LDSA + col0 + 1] + bb4.y + rv.y;
        float x2 = Xs[rl * LDSA + col0 + 2] + bb4.z + rv.z;
        float x3 = Xs[rl * LDSA + col0 + 3] + bb4.w + rv.w;
        float s = x0 + x1 + x2 + x3;
        #pragma unroll
        for (int o = 16; o > 0; o >>= 1) s += __shfl_xor_sync(0xffffffffu, s, o);
        float mean = s * (1.0f / 128.0f);
        float d0 = x0 - mean, d1 = x1 - mean, d2 = x2 - mean, d3 = x3 - mean;
        float v = d0 * d0 + d1 * d1 + d2 * d2 + d3 * d3;
        #pragma unroll
        for (int o = 16; o > 0; o >>= 1) v += __shfl_xor_sync(0xffffffffu, v, o);
        float rs = rsqrtf(v * (1.0f / 128.0f) + 1e-5f);
        float4 y;
        y.x = fmaf(d0 * rs, gg.x, ee.x);
        y.y = fmaf(d1 * rs, gg.y, ee.y);
        y.z = fmaf(d2 * rs, gg.z, ee.z);
        y.w = fmaf(d3 * rs, gg.w, ee.w);
        *(float4*)(Y + (size_t)grow * 128 + col0) = y;
    }
}

// ---------------- GEMM + bias + activation (relu / tanh / none) -------------
// C[M,ND] = act(A[M,KD] @ W[KD,ND] + bias).  n-chunked by gridDim.y.
template <int ACT>
__global__ __launch_bounds__(256, 2)
void gemm_act_kernel(const float* __restrict__ A, const float* __restrict__ W,
                     const float* __restrict__ bias, float* __restrict__ C,
                     int M, int KD, int ND) {
    extern __shared__ float smem[];
    float* As = smem;
    float* Ws = smem + 128 * LDSA;
    int tid = threadIdx.x;
    int lane = tid & 31, wid = tid >> 5, wm = wid >> 2, wn = wid & 3;
    int m0 = blockIdx.x * 128;
    int n0 = blockIdx.y * 128;

    float acc[4][4][4];
    zero_acc(acc);

    for (int kc128 = 0; kc128 < KD / 128; ++kc128) {
        #pragma unroll
        for (int kc = 0; kc < 2; ++kc) {
            __syncthreads();
            if (kc == 0) load_A128(As, A, m0, kc128 * 128, KD, M, tid);
            load_W64(Ws, W, kc128 * 128 + kc * 64, n0, ND, tid);
            __syncthreads();
            mma64(acc, As, Ws, kc * 64, lane, wm, wn);
        }
    }

    #pragma unroll
    for (int mt = 0; mt < 4; ++mt) {
        int r0 = m0 + wm * 64 + mt * 16 + (lane >> 2);
        #pragma unroll
        for (int nt = 0; nt < 4; ++nt) {
            int col = n0 + wn * 32 + nt * 8 + (lane & 3) * 2;
            if (col >= ND) continue;
            float b0 = bias ? bias[col] : 0.f;
            float b1 = bias ? bias[col + 1] : 0.f;
            float v0 = acc[mt][nt][0] + b0, v1 = acc[mt][nt][1] + b1;
            float v2 = acc[mt][nt][2] + b0, v3 = acc[mt][nt][3] + b1;
            if (ACT == 1) {
                v0 = fmaxf(v0, 0.f); v1 = fmaxf(v1, 0.f);
                v2 = fmaxf(v2, 0.f); v3 = fmaxf(v3, 0.f);
            } else if (ACT == 2) {
                v0 = tanhf(v0); v1 = tanhf(v1); v2 = tanhf(v2); v3 = tanhf(v3);
            }
            if (r0 < M)
                *(float2*)(C + (size_t)r0 * ND + col) = make_float2(v0, v1);
            if (r0 + 8 < M)
                *(float2*)(C + (size_t)(r0 + 8) * ND + col) = make_float2(v2, v3);
        }
    }
}

// ---------------- attention: warp per node ----------------------------------
__global__ __launch_bounds__(256)
void attn_kernel(const float* __restrict__ Q, const float* __restrict__ Kp,
                 const float* __restrict__ Vp, const int* __restrict__ nbr,
                 float* __restrict__ O) {
    int node = blockIdx.x * 8 + (threadIdx.x >> 5);
    if (node >= NNODES) return;
    int lane = threadIdx.x & 31;

    float4 q = ((const float4*)(Q + (size_t)node * DMODEL))[lane];

    int nidx[KNBR];
    float s[KNBR];
    #pragma unroll
    for (int j = 0; j < KNBR; ++j) {
        int n = nbr[node * KNBR + j];
        nidx[j] = n;
        bool masked = g_mask[node * KNBR + j] != 0;
        float4 kk = ((const float4*)(Kp + (size_t)n * DMODEL))[lane];
        float d = q.x * kk.x + q.y * kk.y + q.z * kk.z + q.w * kk.w;
        d += __shfl_xor_sync(0xffffffffu, d, 1);
        d += __shfl_xor_sync(0xffffffffu, d, 2);   // 4-lane (one head) reduce
        s[j] = masked ? -1e30f : d * 0.25f;        // dh^-0.5 = 1/sqrt(16)
    }

    float m = s[0];
    #pragma unroll
    for (int j = 1; j < KNBR; ++j) m = fmaxf(m, s[j]);
    float sum = 0.0f;
    #pragma unroll
    for (int j = 0; j < KNBR; ++j) { s[j] = expf(s[j] - m); sum += s[j]; }
    float inv = 1.0f / sum;

    float4 acc = make_float4(0.f, 0.f, 0.f, 0.f);
    #pragma unroll
    for (int j = 0; j < KNBR; ++j) {
        float p = s[j] * inv;
        float4 v = ((const float4*)(Vp + (size_t)nidx[j] * DMODEL))[lane];
        acc.x = fmaf(p, v.x, acc.x);
        acc.y = fmaf(p, v.y, acc.y);
        acc.z = fmaf(p, v.z, acc.z);
        acc.w = fmaf(p, v.w, acc.w);
    }
    ((float4*)(O + (size_t)node * DMODEL))[lane] = acc;
}

// ---------------- launch ------------------------------------------------------
extern "C" void kernel_launch(void* const* d_in, const int* in_sizes, int n_in,
                              void* d_out, int out_size) {
    const float* feat = (const float*)d_in[0];
    const int*   nbr  = (const int*)d_in[1];
    const void*  valid = d_in[2];
    const float* wq1 = (const float*)d_in[3];
    const float* wk1 = (const float*)d_in[4];
    const float* wv1 = (const float*)d_in[5];
    const float* wo1 = (const float*)d_in[6];
    const float* bo1 = (const float*)d_in[7];
    const float* w1a = (const float*)d_in[8];
    const float* b1a = (const float*)d_in[9];
    const float* w1b = (const float*)d_in[10];
    const float* b1b = (const float*)d_in[11];
    const float* g1a = (const float*)d_in[12];
    const float* be1a = (const float*)d_in[13];
    const float* g1b = (const float*)d_in[14];
    const float* be1b = (const float*)d_in[15];
    const float* wq2 = (const float*)d_in[16];
    const float* wk2 = (const float*)d_in[17];
    const float* wv2 = (const float*)d_in[18];
    const float* wo2 = (const float*)d_in[19];
    const float* bo2 = (const float*)d_in[20];
    const float* w2a = (const float*)d_in[21];
    const float* b2a = (const float*)d_in[22];
    const float* w2b = (const float*)d_in[23];
    const float* b2b = (const float*)d_in[24];
    const float* g2a = (const float*)d_in[25];
    const float* be2a = (const float*)d_in[26];
    const float* g2b = (const float*)d_in[27];
    const float* be2b = (const float*)d_in[28];
    const float* w4 = (const float*)d_in[29];
    const float* b4 = (const float*)d_in[30];

    cudaFuncSetAttribute(gemm3_kernel,
                         cudaFuncAttributeMaxDynamicSharedMemorySize, SMEM_BYTES);
    cudaFuncSetAttribute(gemm_ln_kernel<128>,
                         cudaFuncAttributeMaxDynamicSharedMemorySize, SMEM_BYTES);
    cudaFuncSetAttribute(gemm_ln_kernel<256>,
                         cudaFuncAttributeMaxDynamicSharedMemorySize, SMEM_BYTES);
    cudaFuncSetAttribute(gemm_act_kernel<1>,
                         cudaFuncAttributeMaxDynamicSharedMemorySize, SMEM_BYTES);
    cudaFuncSetAttribute(gemm_act_kernel<2>,
                         cudaFuncAttributeMaxDynamicSharedMemorySize, SMEM_BYTES);

    float *pQ, *pK, *pV, *pO, *pX1, *pX2, *pH;
    cudaGetSymbolAddress((void**)&pQ, g_Q);
    cudaGetSymbolAddress((void**)&pK, g_K);
    cudaGetSymbolAddress((void**)&pV, g_V);
    cudaGetSymbolAddress((void**)&pO, g_O);
    cudaGetSymbolAddress((void**)&pX1, g_X1);
    cudaGetSymbolAddress((void**)&pX2, g_X2);
    cudaGetSymbolAddress((void**)&pH, g_H);

    const int M = NNODES;
    const int GB = (M + 127) / 128;      // tensor-core gemm blocks (BM=128)
    const int GW = (M + 7) / 8;          // warp-per-row blocks
    const int GE = (M * KNBR + 255) / 256;

    detect_valid_kernel<<<1, 1>>>((const unsigned int*)valid);
    rowsum_kernel<<<GW, 256>>>(feat);
    edgemask_kernel<<<GE, 256>>>(valid, nbr);

    // ---- layer 1 ----
    gemm3_kernel<<<GB, 256, SMEM_BYTES>>>(feat, wq1, wk1, wv1, pQ, pK, pV, M);
    attn_kernel<<<GW, 256>>>(pQ, pK, pV, nbr, pO);
    gemm_ln_kernel<128><<<GB, 256, SMEM_BYTES>>>(pO, wo1, bo1, feat, g1a, be1a, pX1, M);
    gemm_act_kernel<1><<<dim3(GB, 2), 256, SMEM_BYTES>>>(pX1, w1a, b1a, pH, M, 128, 256);
    gemm_ln_kernel<256><<<GB, 256, SMEM_BYTES>>>(pH, w1b, b1b, pX1, g1b, be1b, pX2, M);

    // ---- layer 2 (q from pX2; k/v from feat) ----
    gemm3_kernel<<<GB, 256, SMEM_BYTES>>>(pX2, wq2, nullptr, nullptr, pQ, nullptr, nullptr, M);
    gemm3_kernel<<<GB, 256, SMEM_BYTES>>>(feat, wk2, wv2, nullptr, pK, pV, nullptr, M);
    attn_kernel<<<GW, 256>>>(pQ, pK, pV, nbr, pO);
    gemm_ln_kernel<128><<<GB, 256, SMEM_BYTES>>>(pO, wo2, bo2, pX2, g2a, be2a, pX1, M);
    gemm_act_kernel<1><<<dim3(GB, 2), 256, SMEM_BYTES>>>(pX1, w2a, b2a, pH, M, 128, 256);
    gemm_ln_kernel<256><<<GB, 256, SMEM_BYTES>>>(pH, w2b, b2b, pX1, g2b, be2b, pX2, M);

    // ---- final head (tanh, ND=64) ----
    gemm_act_kernel<2><<<dim3(GB, 1), 256, SMEM_BYTES>>>(pX2, w4, b4, (float*)d_out, M, 128, 64);
}

// round 10
// speedup vs baseline: 2.7954x; 1.2887x over previous
#include <cuda_runtime.h>
#include <cuda_fp16.h>
#include <math.h>

#define NNODES 300000
#define DMODEL 128
#define KNBR 5

// ---------------- scratch (device globals; no runtime allocation) ----------
__device__ float g_rowsum[NNODES];
__device__ unsigned char g_mask[NNODES * KNBR];
__device__ int g_valid_mode;   // 0 = int32 bools, 1 = uint8 bools, 2 = float bools
__device__ float g_Q[NNODES * DMODEL];
__device__ float g_K[NNODES * DMODEL];
__device__ float g_V[NNODES * DMODEL];
__device__ float g_O[NNODES * DMODEL];
__device__ float g_X1[NNODES * DMODEL];
__device__ float g_X2[NNODES * DMODEL];
__device__ float g_H[NNODES * 2 * DMODEL];

// fp16 weight arena (pre-converted once per launch; w4 padded to 128 cols)
#define OFF_WQ1 0
#define OFF_WK1 16384
#define OFF_WV1 32768
#define OFF_WO1 49152
#define OFF_W1A 65536
#define OFF_W1B 98304
#define OFF_WQ2 131072
#define OFF_WK2 147456
#define OFF_WV2 163840
#define OFF_WO2 180224
#define OFF_W2A 196608
#define OFF_W2B 229376
#define OFF_W4  262144
#define WH_TOTAL 278528
__device__ __half g_Wh[WH_TOTAL];

// ---------------- nbr_valid encoding detection -----------------------------
__global__ void detect_valid_kernel(const unsigned int* v) {
    int all01 = 1, allf = 1;
    for (int t = 0; t < 2048; ++t) {
        unsigned int x = v[t];
        if (x > 1u) all01 = 0;
        if (x != 0u && x != 0x3f800000u) allf = 0;
    }
    g_valid_mode = all01 ? 0 : (allf ? 2 : 1);
}

// ---------------- per-row feat sum (for the ==0 mask) -----------------------
__global__ void rowsum_kernel(const float* __restrict__ feat) {
    int row = blockIdx.x * 8 + (threadIdx.x >> 5);
    if (row >= NNODES) return;
    int lane = threadIdx.x & 31;
    float4 v = ((const float4*)(feat + (size_t)row * DMODEL))[lane];
    float s = v.x + v.y + v.z + v.w;
    #pragma unroll
    for (int o = 16; o > 0; o >>= 1) s += __shfl_xor_sync(0xffffffffu, s, o);
    if (lane == 0) g_rowsum[row] = s;
}

// ---------------- per-edge mask ---------------------------------------------
__global__ void edgemask_kernel(const void* __restrict__ valid_raw,
                                const int* __restrict__ nbr) {
    int e = blockIdx.x * blockDim.x + threadIdx.x;
    if (e >= NNODES * KNBR) return;
    int mode = g_valid_mode;
    bool valid;
    if (mode == 1)      valid = ((const unsigned char*)valid_raw)[e] != 0;
    else if (mode == 2) valid = ((const float*)valid_raw)[e] != 0.0f;
    else                valid = ((const int*)valid_raw)[e] != 0;
    bool masked = (!valid) || (g_rowsum[nbr[e]] == 0.0f);
    g_mask[e] = masked ? 1 : 0;
}

// ---------------- weight fp32 -> fp16 conversion -----------------------------
__global__ void convert_w_kernel(
    const float* wq1, const float* wk1, const float* wv1, const float* wo1,
    const float* w1a, const float* w1b,
    const float* wq2, const float* wk2, const float* wv2, const float* wo2,
    const float* w2a, const float* w2b, const float* w4) {
    int w = blockIdx.y;
    int e = blockIdx.x * 256 + threadIdx.x;
    if (w == 12) {   // w4: [128,64] -> padded [128,128]
        if (e < 16384) {
            int r = e >> 7, c = e & 127;
            g_Wh[OFF_W4 + e] = (c < 64) ? __float2half_rn(w4[(r << 6) + c])
                                        : __float2half_rn(0.0f);
        }
        return;
    }
    const float* src; int n; int off;
    switch (w) {
        case 0:  src = wq1; n = 16384; off = OFF_WQ1; break;
        case 1:  src = wk1; n = 16384; off = OFF_WK1; break;
        case 2:  src = wv1; n = 16384; off = OFF_WV1; break;
        case 3:  src = wo1; n = 16384; off = OFF_WO1; break;
        case 4:  src = w1a; n = 32768; off = OFF_W1A; break;
        case 5:  src = w1b; n = 32768; off = OFF_W1B; break;
        case 6:  src = wq2; n = 16384; off = OFF_WQ2; break;
        case 7:  src = wk2; n = 16384; off = OFF_WK2; break;
        case 8:  src = wv2; n = 16384; off = OFF_WV2; break;
        case 9:  src = wo2; n = 16384; off = OFF_WO2; break;
        case 10: src = w2a; n = 32768; off = OFF_W2A; break;
        default: src = w2b; n = 32768; off = OFF_W2B; break;
    }
    if (e < n) g_Wh[off + e] = __float2half_rn(src[e]);
}

// ============================================================================
// fp16 tensor-core GEMM core.
//   Block tile BM=128 x BN=128, 256 threads = 8 warps (2m x 4n),
//   warp tile 64x32, mma m16n8k16 (mt=4, nt=4), f32 accumulators.
//   A: fp32 -> fp16 via LDG+cvt+STS, staged 128x128 halfs, row stride 136
//      halfs (272 B; 272/16 = 17, odd -> ldmatrix conflict-free).
//   W: pre-converted fp16, streamed via cp.async into 2 x 64-deep k-chunk
//      buffers (double-buffered pipeline), same 136-half stride.
//   smem = (128*136 + 2*64*136)*2 = 69632 B -> 2 CTAs/SM.
// ============================================================================
#define LDA 136
#define LDB 136
#define AS_HALFS (128 * LDA)
#define WB_HALFS (64 * LDB)
#define SMEM_BYTES ((AS_HALFS + 2 * WB_HALFS) * 2)

__device__ __forceinline__ unsigned smem_u32(const void* p) {
    return (unsigned)__cvta_generic_to_shared(p);
}
__device__ __forceinline__ void ldm_x4(unsigned& r0, unsigned& r1, unsigned& r2,
                                       unsigned& r3, unsigned addr) {
    asm volatile("ldmatrix.sync.aligned.m8n8.x4.shared.b16 {%0,%1,%2,%3}, [%4];"
                 : "=r"(r0), "=r"(r1), "=r"(r2), "=r"(r3) : "r"(addr));
}
__device__ __forceinline__ void ldm_x2t(unsigned& r0, unsigned& r1, unsigned addr) {
    asm volatile("ldmatrix.sync.aligned.m8n8.x2.trans.shared.b16 {%0,%1}, [%2];"
                 : "=r"(r0), "=r"(r1) : "r"(addr));
}
__device__ __forceinline__ void mma16(float* c, unsigned a0, unsigned a1,
                                      unsigned a2, unsigned a3,
                                      unsigned b0, unsigned b1) {
    asm volatile(
        "mma.sync.aligned.m16n8k16.row.col.f32.f16.f16.f32 "
        "{%0,%1,%2,%3}, {%4,%5,%6,%7}, {%8,%9}, {%0,%1,%2,%3};\n"
        : "+f"(c[0]), "+f"(c[1]), "+f"(c[2]), "+f"(c[3])
        : "r"(a0), "r"(a1), "r"(a2), "r"(a3), "r"(b0), "r"(b1));
}
__device__ __forceinline__ void cp16(void* dst, const void* src) {
    unsigned d = smem_u32(dst);
    asm volatile("cp.async.ca.shared.global [%0], [%1], 16;" :: "r"(d), "l"(src));
}
__device__ __forceinline__ void cp_commit() {
    asm volatile("cp.async.commit_group;");
}
template <int N>
__device__ __forceinline__ void cp_wait() {
    asm volatile("cp.async.wait_group %0;" :: "n"(N));
}

// Load 128-row x 128-k A chunk (fp32 global -> fp16 smem).
__device__ __forceinline__ void load_A_h(__half* As, const float* A, int m0,
                                         int kc0, int KD, int M, int tid) {
    #pragma unroll 4
    for (int i = tid; i < 128 * 32; i += 256) {
        int r = i >> 5, c4 = (i & 31) * 4;
        int grow = m0 + r;
        float4 v = make_float4(0.f, 0.f, 0.f, 0.f);
        if (grow < M)
            v = *(const float4*)(A + (size_t)grow * KD + kc0 + c4);
        __half2* d = (__half2*)(As + r * LDA + c4);
        d[0] = __floats2half2_rn(v.x, v.y);
        d[1] = __floats2half2_rn(v.z, v.w);
    }
}

// Stream a 64-krow x 128-ncol fp16 W chunk via cp.async. NDW = row stride.
__device__ __forceinline__ void load_W_cp(__half* Wb, const __half* W, int kc0,
                                          int n0, int NDW, int tid) {
    #pragma unroll
    for (int i = tid; i < 1024; i += 256) {
        int kr = i >> 4, c8 = (i & 15) * 8;
        cp16(Wb + kr * LDB + c8, W + (size_t)(kc0 + kr) * NDW + n0 + c8);
    }
}

// 64-deep k-chunk of MMAs. kbase = k offset within As columns (0 or 64).
__device__ __forceinline__ void mma_h64(float (&acc)[4][4][4], const __half* As,
                                        const __half* Wb, int kbase,
                                        int lane, int wm, int wn) {
    int row_off = lane & 15;
    int ko = (lane >= 16) ? 8 : 0;
    #pragma unroll
    for (int kk = 0; kk < 64; kk += 16) {
        unsigned a[4][4];
        #pragma unroll
        for (int mt = 0; mt < 4; ++mt) {
            unsigned addr = smem_u32(As + (wm * 64 + mt * 16 + row_off) * LDA +
                                     kbase + kk + ko);
            ldm_x4(a[mt][0], a[mt][1], a[mt][2], a[mt][3], addr);
        }
        #pragma unroll
        for (int nt = 0; nt < 4; ++nt) {
            unsigned b0, b1;
            unsigned baddr = smem_u32(Wb + (kk + (lane & 15)) * LDB +
                                      wn * 32 + nt * 8);
            ldm_x2t(b0, b1, baddr);
            #pragma unroll
            for (int mt = 0; mt < 4; ++mt)
                mma16(acc[mt][nt], a[mt][0], a[mt][1], a[mt][2], a[mt][3], b0, b1);
        }
    }
}

__device__ __forceinline__ void zero_acc(float (&acc)[4][4][4]) {
    #pragma unroll
    for (int mt = 0; mt < 4; ++mt)
        #pragma unroll
        for (int nt = 0; nt < 4; ++nt)
            #pragma unroll
            for (int q = 0; q < 4; ++q) acc[mt][nt][q] = 0.f;
}

// ---------------- fused multi-output GEMM (QKV): C_j = A @ W_j, KD=128 ------
__global__ __launch_bounds__(256, 2)
void gemm3_kernel(const float* __restrict__ A,
                  const __half* __restrict__ W0, const __half* __restrict__ W1,
                  const __half* __restrict__ W2,
                  float* __restrict__ C0, float* __restrict__ C1,
                  float* __restrict__ C2, int M) {
    extern __shared__ __half smh[];
    __half* As = smh;
    __half* Wb0 = smh + AS_HALFS;
    __half* Wb1 = smh + AS_HALFS + WB_HALFS;
    int tid = threadIdx.x;
    int lane = tid & 31, wid = tid >> 5, wm = wid >> 2, wn = wid & 3;
    int m0 = blockIdx.x * 128;

    const __half* Wl[3] = {W0, W1, W2};
    float* Cl[3] = {C0, C1, C2};
    int nW = W1 ? (W2 ? 3 : 2) : 1;
    int T = nW * 2;

    load_A_h(As, A, m0, 0, 128, M, tid);
    load_W_cp(Wb0, Wl[0], 0, 0, 128, tid);
    cp_commit();

    float acc[4][4][4];
    for (int t = 0; t < T; ++t) {
        int j = t >> 1, c = t & 1;
        if (c == 0) zero_acc(acc);
        if (t + 1 < T) {
            int j1 = (t + 1) >> 1, c1 = (t + 1) & 1;
            load_W_cp((t & 1) ? Wb0 : Wb1, Wl[j1], c1 * 64, 0, 128, tid);
            cp_commit();
            cp_wait<1>();
        } else {
            cp_wait<0>();
        }
        __syncthreads();
        mma_h64(acc, As, (t & 1) ? Wb1 : Wb0, c * 64, lane, wm, wn);
        __syncthreads();
        if (c == 1) {
            float* C = Cl[j];
            #pragma unroll
            for (int mt = 0; mt < 4; ++mt) {
                int r0 = m0 + wm * 64 + mt * 16 + (lane >> 2);
                #pragma unroll
                for (int nt = 0; nt < 4; ++nt) {
                    int col = wn * 32 + nt * 8 + (lane & 3) * 2;
                    if (r0 < M)
                        *(float2*)(C + (size_t)r0 * 128 + col) =
                            make_float2(acc[mt][nt][0], acc[mt][nt][1]);
                    if (r0 + 8 < M)
                        *(float2*)(C + (size_t)(r0 + 8) * 128 + col) =
                            make_float2(acc[mt][nt][2], acc[mt][nt][3]);
                }
            }
        }
    }
}

// ---------------- GEMM + bias + residual + LayerNorm fused ------------------
// Y = LN(R + A@W + bias) * g + be.  ND = 128 (full row in block).
template <int KD>
__global__ __launch_bounds__(256, 2)
void gemm_ln_kernel(const float* __restrict__ A, const __half* __restrict__ W,
                    const float* __restrict__ bias, const float* __restrict__ R,
                    const float* __restrict__ g, const float* __restrict__ be,
                    float* __restrict__ Y, int M) {
    extern __shared__ __half smh[];
    __half* As = smh;
    __half* Wb0 = smh + AS_HALFS;
    __half* Wb1 = smh + AS_HALFS + WB_HALFS;
    int tid = threadIdx.x;
    int lane = tid & 31, wid = tid >> 5, wm = wid >> 2, wn = wid & 3;
    int m0 = blockIdx.x * 128;
    constexpr int T = KD / 64;

    float acc[4][4][4];
    zero_acc(acc);

    load_A_h(As, A, m0, 0, KD, M, tid);
    load_W_cp(Wb0, W, 0, 0, 128, tid);
    cp_commit();

    #pragma unroll
    for (int t = 0; t < T; ++t) {
        if (t + 1 < T) {
            load_W_cp((t & 1) ? Wb0 : Wb1, W, (t + 1) * 64, 0, 128, tid);
            cp_commit();
            cp_wait<1>();
        } else {
            cp_wait<0>();
        }
        if (KD == 256 && t == 2)     // restage A for k 128..255 (prev sync covers)
            load_A_h(As, A, m0, 128, KD, M, tid);
        __syncthreads();
        mma_h64(acc, As, (t & 1) ? Wb1 : Wb0, (t & 1) * 64, lane, wm, wn);
        __syncthreads();
    }

    // Stage pre-LN values into smem as fp32 (stride 132 over whole smem)
    float* Xs = (float*)smh;
    #pragma unroll
    for (int mt = 0; mt < 4; ++mt) {
        int r0 = wm * 64 + mt * 16 + (lane >> 2);
        #pragma unroll
        for (int nt = 0; nt < 4; ++nt) {
            int col = wn * 32 + nt * 8 + (lane & 3) * 2;
            *(float2*)(Xs + r0 * 132 + col) = make_float2(acc[mt][nt][0], acc[mt][nt][1]);
            *(float2*)(Xs + (r0 + 8) * 132 + col) = make_float2(acc[mt][nt][2], acc[mt][nt][3]);
        }
    }
    __syncthreads();

    // LayerNorm: warp per row, 16 rows per warp, lane owns 4 cols.
    int col0 = lane * 4;
    float4 bb4 = *(const float4*)(bias + col0);
    float4 gg = *(const float4*)(g + col0);
    float4 ee = *(const float4*)(be + col0);
    #pragma unroll
    for (int rr = 0; rr < 16; ++rr) {
        int rl = wid * 16 + rr;
        int grow = m0 + rl;
        if (grow >= M) break;
        float4 rv = *(const float4*)(R + (size_t)grow * 128 + col0);
        float x0 = Xs[rl * 132 + col0 + 0] + bb4.x + rv.x;
        float x1 = Xs[rl * 132 + col0 + 1] + bb4.y + rv.y;
        float x2 = Xs[rl * 132 + col0 + 2] + bb4.z + rv.z;
        float x3 = Xs[rl * 132 + col0 + 3] + bb4.w + rv.w;
        float s = x0 + x1 + x2 + x3;
        #pragma unroll
        for (int o = 16; o > 0; o >>= 1) s += __shfl_xor_sync(0xffffffffu, s, o);
        float mean = s * (1.0f / 128.0f);
        float d0 = x0 - mean, d1 = x1 - mean, d2 = x2 - mean, d3 = x3 - mean;
        float v = d0 * d0 + d1 * d1 + d2 * d2 + d3 * d3;
        #pragma unroll
        for (int o = 16; o > 0; o >>= 1) v += __shfl_xor_sync(0xffffffffu, v, o);
        float rs = rsqrtf(v * (1.0f / 128.0f) + 1e-5f);
        float4 y;
        y.x = fmaf(d0 * rs, gg.x, ee.x);
        y.y = fmaf(d1 * rs, gg.y, ee.y);
        y.z = fmaf(d2 * rs, gg.z, ee.z);
        y.w = fmaf(d3 * rs, gg.w, ee.w);
        *(float4*)(Y + (size_t)grow * 128 + col0) = y;
    }
}

// ---------------- GEMM + bias + activation (relu / tanh / none) -------------
// C[M,ND] = act(A[M,128] @ W + bias). W row stride NDW; n-chunk via gridDim.y.
template <int ACT>
__global__ __launch_bounds__(256, 2)
void gemm_act_kernel(const float* __restrict__ A, const __half* __restrict__ W,
                     const float* __restrict__ bias, float* __restrict__ C,
                     int M, int NDW, int ND) {
    extern __shared__ __half smh[];
    __half* As = smh;
    __half* Wb0 = smh + AS_HALFS;
    __half* Wb1 = smh + AS_HALFS + WB_HALFS;
    int tid = threadIdx.x;
    int lane = tid & 31, wid = tid >> 5, wm = wid >> 2, wn = wid & 3;
    int m0 = blockIdx.x * 128;
    int n0 = blockIdx.y * 128;

    float acc[4][4][4];
    zero_acc(acc);

    load_A_h(As, A, m0, 0, 128, M, tid);
    load_W_cp(Wb0, W, 0, n0, NDW, tid);
    cp_commit();

    #pragma unroll
    for (int t = 0; t < 2; ++t) {
        if (t == 0) {
            load_W_cp(Wb1, W, 64, n0, NDW, tid);
            cp_commit();
            cp_wait<1>();
        } else {
            cp_wait<0>();
        }
        __syncthreads();
        mma_h64(acc, As, (t & 1) ? Wb1 : Wb0, t * 64, lane, wm, wn);
        __syncthreads();
    }

    #pragma unroll
    for (int mt = 0; mt < 4; ++mt) {
        int r0 = m0 + wm * 64 + mt * 16 + (lane >> 2);
        #pragma unroll
        for (int nt = 0; nt < 4; ++nt) {
            int col = n0 + wn * 32 + nt * 8 + (lane & 3) * 2;
            if (col >= ND) continue;
            float b0 = bias ? bias[col] : 0.f;
            float b1 = bias ? bias[col + 1] : 0.f;
            float v0 = acc[mt][nt][0] + b0, v1 = acc[mt][nt][1] + b1;
            float v2 = acc[mt][nt][2] + b0, v3 = acc[mt][nt][3] + b1;
            if (ACT == 1) {
                v0 = fmaxf(v0, 0.f); v1 = fmaxf(v1, 0.f);
                v2 = fmaxf(v2, 0.f); v3 = fmaxf(v3, 0.f);
            } else if (ACT == 2) {
                v0 = tanhf(v0); v1 = tanhf(v1); v2 = tanhf(v2); v3 = tanhf(v3);
            }
            if (r0 < M)
                *(float2*)(C + (size_t)r0 * ND + col) = make_float2(v0, v1);
            if (r0 + 8 < M)
                *(float2*)(C + (size_t)(r0 + 8) * ND + col) = make_float2(v2, v3);
        }
    }
}

// ---------------- attention: warp per node ----------------------------------
__global__ __launch_bounds__(256)
void attn_kernel(const float* __restrict__ Q, const float* __restrict__ Kp,
                 const float* __restrict__ Vp, const int* __restrict__ nbr,
                 float* __restrict__ O) {
    int node = blockIdx.x * 8 + (threadIdx.x >> 5);
    if (node >= NNODES) return;
    int lane = threadIdx.x & 31;

    float4 q = ((const float4*)(Q + (size_t)node * DMODEL))[lane];

    int nidx[KNBR];
    float s[KNBR];
    #pragma unroll
    for (int j = 0; j < KNBR; ++j) {
        int n = nbr[node * KNBR + j];
        nidx[j] = n;
        bool masked = g_mask[node * KNBR + j] != 0;
        float4 kk = ((const float4*)(Kp + (size_t)n * DMODEL))[lane];
        float d = q.x * kk.x + q.y * kk.y + q.z * kk.z + q.w * kk.w;
        d += __shfl_xor_sync(0xffffffffu, d, 1);
        d += __shfl_xor_sync(0xffffffffu, d, 2);   // 4-lane (one head) reduce
        s[j] = masked ? -1e30f : d * 0.25f;        // dh^-0.5 = 1/sqrt(16)
    }

    float m = s[0];
    #pragma unroll
    for (int j = 1; j < KNBR; ++j) m = fmaxf(m, s[j]);
    float sum = 0.0f;
    #pragma unroll
    for (int j = 0; j < KNBR; ++j) { s[j] = expf(s[j] - m); sum += s[j]; }
    float inv = 1.0f / sum;

    float4 acc = make_float4(0.f, 0.f, 0.f, 0.f);
    #pragma unroll
    for (int j = 0; j < KNBR; ++j) {
        float p = s[j] * inv;
        float4 v = ((const float4*)(Vp + (size_t)nidx[j] * DMODEL))[lane];
        acc.x = fmaf(p, v.x, acc.x);
        acc.y = fmaf(p, v.y, acc.y);
        acc.z = fmaf(p, v.z, acc.z);
        acc.w = fmaf(p, v.w, acc.w);
    }
    ((float4*)(O + (size_t)node * DMODEL))[lane] = acc;
}

// ---------------- launch ------------------------------------------------------
extern "C" void kernel_launch(void* const* d_in, const int* in_sizes, int n_in,
                              void* d_out, int out_size) {
    const float* feat = (const float*)d_in[0];
    const int*   nbr  = (const int*)d_in[1];
    const void*  valid = d_in[2];
    const float* wq1 = (const float*)d_in[3];
    const float* wk1 = (const float*)d_in[4];
    const float* wv1 = (const float*)d_in[5];
    const float* wo1 = (const float*)d_in[6];
    const float* bo1 = (const float*)d_in[7];
    const float* w1a = (const float*)d_in[8];
    const float* b1a = (const float*)d_in[9];
    const float* w1b = (const float*)d_in[10];
    const float* b1b = (const float*)d_in[11];
    const float* g1a = (const float*)d_in[12];
    const float* be1a = (const float*)d_in[13];
    const float* g1b = (const float*)d_in[14];
    const float* be1b = (const float*)d_in[15];
    const float* wq2 = (const float*)d_in[16];
    const float* wk2 = (const float*)d_in[17];
    const float* wv2 = (const float*)d_in[18];
    const float* wo2 = (const float*)d_in[19];
    const float* bo2 = (const float*)d_in[20];
    const float* w2a = (const float*)d_in[21];
    const float* b2a = (const float*)d_in[22];
    const float* w2b = (const float*)d_in[23];
    const float* b2b = (const float*)d_in[24];
    const float* g2a = (const float*)d_in[25];
    const float* be2a = (const float*)d_in[26];
    const float* g2b = (const float*)d_in[27];
    const float* be2b = (const float*)d_in[28];
    const float* w4 = (const float*)d_in[29];
    const float* b4 = (const float*)d_in[30];

    cudaFuncSetAttribute(gemm3_kernel,
                         cudaFuncAttributeMaxDynamicSharedMemorySize, SMEM_BYTES);
    cudaFuncSetAttribute(gemm_ln_kernel<128>,
                         cudaFuncAttributeMaxDynamicSharedMemorySize, SMEM_BYTES);
    cudaFuncSetAttribute(gemm_ln_kernel<256>,
                         cudaFuncAttributeMaxDynamicSharedMemorySize, SMEM_BYTES);
    cudaFuncSetAttribute(gemm_act_kernel<1>,
                         cudaFuncAttributeMaxDynamicSharedMemorySize, SMEM_BYTES);
    cudaFuncSetAttribute(gemm_act_kernel<2>,
                         cudaFuncAttributeMaxDynamicSharedMemorySize, SMEM_BYTES);

    float *pQ, *pK, *pV, *pO, *pX1, *pX2, *pH;
    __half* pW;
    cudaGetSymbolAddress((void**)&pQ, g_Q);
    cudaGetSymbolAddress((void**)&pK, g_K);
    cudaGetSymbolAddress((void**)&pV, g_V);
    cudaGetSymbolAddress((void**)&pO, g_O);
    cudaGetSymbolAddress((void**)&pX1, g_X1);
    cudaGetSymbolAddress((void**)&pX2, g_X2);
    cudaGetSymbolAddress((void**)&pH, g_H);
    cudaGetSymbolAddress((void**)&pW, g_Wh);

    const int M = NNODES;
    const int GB = (M + 127) / 128;      // tensor-core gemm blocks (BM=128)
    const int GW = (M + 7) / 8;          // warp-per-row blocks
    const int GE = (M * KNBR + 255) / 256;

    detect_valid_kernel<<<1, 1>>>((const unsigned int*)valid);
    rowsum_kernel<<<GW, 256>>>(feat);
    edgemask_kernel<<<GE, 256>>>(valid, nbr);
    convert_w_kernel<<<dim3(128, 13), 256>>>(wq1, wk1, wv1, wo1, w1a, w1b,
                                             wq2, wk2, wv2, wo2, w2a, w2b, w4);

    // ---- layer 1 ----
    gemm3_kernel<<<GB, 256, SMEM_BYTES>>>(feat, pW + OFF_WQ1, pW + OFF_WK1,
                                          pW + OFF_WV1, pQ, pK, pV, M);
    attn_kernel<<<GW, 256>>>(pQ, pK, pV, nbr, pO);
    gemm_ln_kernel<128><<<GB, 256, SMEM_BYTES>>>(pO, pW + OFF_WO1, bo1, feat,
                                                 g1a, be1a, pX1, M);
    gemm_act_kernel<1><<<dim3(GB, 2), 256, SMEM_BYTES>>>(pX1, pW + OFF_W1A, b1a,
                                                         pH, M, 256, 256);
    gemm_ln_kernel<256><<<GB, 256, SMEM_BYTES>>>(pH, pW + OFF_W1B, b1b, pX1,
                                                 g1b, be1b, pX2, M);

    // ---- layer 2 (q from pX2; k/v from feat) ----
    gemm3_kernel<<<GB, 256, SMEM_BYTES>>>(pX2, pW + OFF_WQ2, nullptr, nullptr,
                                          pQ, nullptr, nullptr, M);
    gemm3_kernel<<<GB, 256, SMEM_BYTES>>>(feat, pW + OFF_WK2, pW + OFF_WV2,
                                          nullptr, pK, pV, nullptr, M);
    attn_kernel<<<GW, 256>>>(pQ, pK, pV, nbr, pO);
    gemm_ln_kernel<128><<<GB, 256, SMEM_BYTES>>>(pO, pW + OFF_WO2, bo2, pX2,
                                                 g2a, be2a, pX1, M);
    gemm_act_kernel<1><<<dim3(GB, 2), 256, SMEM_BYTES>>>(pX1, pW + OFF_W2A, b2a,
                                                         pH, M, 256, 256);
    gemm_ln_kernel<256><<<GB, 256, SMEM_BYTES>>>(pH, pW + OFF_W2B, b2b, pX1,
                                                 g2b, be2b, pX2, M);

    // ---- final head (tanh, ND=64, padded weight) ----
    gemm_act_kernel<2><<<dim3(GB, 1), 256, SMEM_BYTES>>>(pX2, pW + OFF_W4, b4,
                                                         (float*)d_out, M, 128, 64);
}

// round 13
// speedup vs baseline: 3.8413x; 1.3742x over previous
#include <cuda_runtime.h>
#include <cuda_fp16.h>
#include <math.h>

#define NNODES 300000
#define DMODEL 128
#define KNBR 5

// ---------------- scratch (device globals; no runtime allocation) ----------
__device__ float g_rowsum[NNODES];
__device__ unsigned char g_mask[NNODES * KNBR];
__device__ int g_valid_mode;   // 0 = int32 bools, 1 = uint8 bools, 2 = float bools
__device__ __half g_featH[NNODES * DMODEL];
__device__ __half g_Q[NNODES * DMODEL];
__device__ __half g_K[NNODES * DMODEL];
__device__ __half g_V[NNODES * DMODEL];
__device__ __half g_O[NNODES * DMODEL];
__device__ __half g_X1[NNODES * DMODEL];
__device__ __half g_X2[NNODES * DMODEL];
__device__ __half g_H[NNODES * 2 * DMODEL];

// fp16 weight arena (pre-converted once per launch; w4 padded to 128 cols)
#define OFF_WQ1 0
#define OFF_WK1 16384
#define OFF_WV1 32768
#define OFF_WO1 49152
#define OFF_W1A 65536
#define OFF_W1B 98304
#define OFF_WQ2 131072
#define OFF_WK2 147456
#define OFF_WV2 163840
#define OFF_WO2 180224
#define OFF_W2A 196608
#define OFF_W2B 229376
#define OFF_W4  262144
#define WH_TOTAL 278528
__device__ __half g_Wh[WH_TOTAL];

// ---------------- nbr_valid encoding detection -----------------------------
__global__ void detect_valid_kernel(const unsigned int* v) {
    int all01 = 1, allf = 1;
    for (int t = 0; t < 2048; ++t) {
        unsigned int x = v[t];
        if (x > 1u) all01 = 0;
        if (x != 0u && x != 0x3f800000u) allf = 0;
    }
    g_valid_mode = all01 ? 0 : (allf ? 2 : 1);
}

// ---------------- per-row feat sum + fp16 conversion -------------------------
__global__ void prep_feat_kernel(const float* __restrict__ feat) {
    int row = blockIdx.x * 8 + (threadIdx.x >> 5);
    if (row >= NNODES) return;
    int lane = threadIdx.x & 31;
    float4 v = ((const float4*)(feat + (size_t)row * DMODEL))[lane];
    float s = v.x + v.y + v.z + v.w;
    #pragma unroll
    for (int o = 16; o > 0; o >>= 1) s += __shfl_xor_sync(0xffffffffu, s, o);
    if (lane == 0) g_rowsum[row] = s;
    __half2 h0 = __floats2half2_rn(v.x, v.y);
    __half2 h1 = __floats2half2_rn(v.z, v.w);
    uint2 u;
    u.x = *(unsigned*)&h0;
    u.y = *(unsigned*)&h1;
    ((uint2*)(g_featH + (size_t)row * DMODEL))[lane] = u;
}

// ---------------- per-edge mask ---------------------------------------------
__global__ void edgemask_kernel(const void* __restrict__ valid_raw,
                                const int* __restrict__ nbr) {
    int e = blockIdx.x * blockDim.x + threadIdx.x;
    if (e >= NNODES * KNBR) return;
    int mode = g_valid_mode;
    bool valid;
    if (mode == 1)      valid = ((const unsigned char*)valid_raw)[e] != 0;
    else if (mode == 2) valid = ((const float*)valid_raw)[e] != 0.0f;
    else                valid = ((const int*)valid_raw)[e] != 0;
    bool masked = (!valid) || (g_rowsum[nbr[e]] == 0.0f);
    g_mask[e] = masked ? 1 : 0;
}

// ---------------- weight fp32 -> fp16 conversion -----------------------------
__global__ void convert_w_kernel(
    const float* wq1, const float* wk1, const float* wv1, const float* wo1,
    const float* w1a, const float* w1b,
    const float* wq2, const float* wk2, const float* wv2, const float* wo2,
    const float* w2a, const float* w2b, const float* w4) {
    int w = blockIdx.y;
    int e = blockIdx.x * 256 + threadIdx.x;
    if (w == 12) {   // w4: [128,64] -> padded [128,128]
        if (e < 16384) {
            int r = e >> 7, c = e & 127;
            g_Wh[OFF_W4 + e] = (c < 64) ? __float2half_rn(w4[(r << 6) + c])
                                        : __float2half_rn(0.0f);
        }
        return;
    }
    const float* src; int n; int off;
    switch (w) {
        case 0:  src = wq1; n = 16384; off = OFF_WQ1; break;
        case 1:  src = wk1; n = 16384; off = OFF_WK1; break;
        case 2:  src = wv1; n = 16384; off = OFF_WV1; break;
        case 3:  src = wo1; n = 16384; off = OFF_WO1; break;
        case 4:  src = w1a; n = 32768; off = OFF_W1A; break;
        case 5:  src = w1b; n = 32768; off = OFF_W1B; break;
        case 6:  src = wq2; n = 16384; off = OFF_WQ2; break;
        case 7:  src = wk2; n = 16384; off = OFF_WK2; break;
        case 8:  src = wv2; n = 16384; off = OFF_WV2; break;
        case 9:  src = wo2; n = 16384; off = OFF_WO2; break;
        case 10: src = w2a; n = 32768; off = OFF_W2A; break;
        default: src = w2b; n = 32768; off = OFF_W2B; break;
    }
    if (e < n) g_Wh[off + e] = __float2half_rn(src[e]);
}

// ============================================================================
// fp16 tensor-core GEMM core (all-fp16 operands, fp32 accum).
//   Block tile BM=128 x BN=128, 256 threads = 8 warps (2m x 4n),
//   warp tile 64x32, mma m16n8k16 (mt=4, nt=4).
//   A and W both fp16 in GMEM -> both streamed via cp.async.
//   smem = (128*136 + 2*64*136)*2 = 69632 B -> 2 CTAs/SM.
// ============================================================================
#define LDA 136
#define LDB 136
#define AS_HALFS (128 * LDA)
#define WB_HALFS (64 * LDB)
#define SMEM_BYTES ((AS_HALFS + 2 * WB_HALFS) * 2)

__device__ __forceinline__ unsigned smem_u32(const void* p) {
    return (unsigned)__cvta_generic_to_shared(p);
}
__device__ __forceinline__ void ldm_x4(unsigned& r0, unsigned& r1, unsigned& r2,
                                       unsigned& r3, unsigned addr) {
    asm volatile("ldmatrix.sync.aligned.m8n8.x4.shared.b16 {%0,%1,%2,%3}, [%4];"
                 : "=r"(r0), "=r"(r1), "=r"(r2), "=r"(r3) : "r"(addr));
}
__device__ __forceinline__ void ldm_x2t(unsigned& r0, unsigned& r1, unsigned addr) {
    asm volatile("ldmatrix.sync.aligned.m8n8.x2.trans.shared.b16 {%0,%1}, [%2];"
                 : "=r"(r0), "=r"(r1) : "r"(addr));
}
__device__ __forceinline__ void mma16(float* c, unsigned a0, unsigned a1,
                                      unsigned a2, unsigned a3,
                                      unsigned b0, unsigned b1) {
    asm volatile(
        "mma.sync.aligned.m16n8k16.row.col.f32.f16.f16.f32 "
        "{%0,%1,%2,%3}, {%4,%5,%6,%7}, {%8,%9}, {%0,%1,%2,%3};\n"
        : "+f"(c[0]), "+f"(c[1]), "+f"(c[2]), "+f"(c[3])
        : "r"(a0), "r"(a1), "r"(a2), "r"(a3), "r"(b0), "r"(b1));
}
__device__ __forceinline__ void cp16(void* dst, const void* src) {
    unsigned d = smem_u32(dst);
    asm volatile("cp.async.ca.shared.global [%0], [%1], 16;" :: "r"(d), "l"(src));
}
// Zero-fill variant: copies srcsz bytes (0 or 16), zero-fills the rest.
__device__ __forceinline__ void cp16z(void* dst, const void* src, int srcsz) {
    unsigned d = smem_u32(dst);
    asm volatile("cp.async.ca.shared.global [%0], [%1], 16, %2;"
                 :: "r"(d), "l"(src), "r"(srcsz));
}
__device__ __forceinline__ void cp_commit() {
    asm volatile("cp.async.commit_group;");
}
template <int N>
__device__ __forceinline__ void cp_wait() {
    asm volatile("cp.async.wait_group %0;" :: "n"(N));
}
__device__ __forceinline__ unsigned pack_h2(float a, float b) {
    __half2 h = __floats2half2_rn(a, b);
    return *(unsigned*)&h;
}

// Stream a 128-row x 128-col fp16 A chunk via cp.async (zero-fill rows >= M).
__device__ __forceinline__ void load_A_cp(__half* As, const __half* A, int m0,
                                          int kc0, int KD, int M, int tid) {
    #pragma unroll
    for (int i = tid; i < 128 * 16; i += 256) {
        int r = i >> 4, c8 = (i & 15) * 8;
        int grow = m0 + r;
        int ok = (grow < M) ? 16 : 0;
        int srow = (grow < M) ? grow : (M - 1);
        cp16z(As + r * LDA + c8, A + (size_t)srow * KD + kc0 + c8, ok);
    }
}

// Stream a 64-krow x 128-ncol fp16 W chunk via cp.async. NDW = row stride.
__device__ __forceinline__ void load_W_cp(__half* Wb, const __half* W, int kc0,
                                          int n0, int NDW, int tid) {
    #pragma unroll
    for (int i = tid; i < 1024; i += 256) {
        int kr = i >> 4, c8 = (i & 15) * 8;
        cp16(Wb + kr * LDB + c8, W + (size_t)(kc0 + kr) * NDW + n0 + c8);
    }
}

// 64-deep k-chunk of MMAs. kbase = k offset within As columns (0 or 64).
__device__ __forceinline__ void mma_h64(float (&acc)[4][4][4], const __half* As,
                                        const __half* Wb, int kbase,
                                        int lane, int wm, int wn) {
    int row_off = lane & 15;
    int ko = (lane >= 16) ? 8 : 0;
    #pragma unroll
    for (int kk = 0; kk < 64; kk += 16) {
        unsigned a[4][4];
        #pragma unroll
        for (int mt = 0; mt < 4; ++mt) {
            unsigned addr = smem_u32(As + (wm * 64 + mt * 16 + row_off) * LDA +
                                     kbase + kk + ko);
            ldm_x4(a[mt][0], a[mt][1], a[mt][2], a[mt][3], addr);
        }
        #pragma unroll
        for (int nt = 0; nt < 4; ++nt) {
            unsigned b0, b1;
            unsigned baddr = smem_u32(Wb + (kk + (lane & 15)) * LDB +
                                      wn * 32 + nt * 8);
            ldm_x2t(b0, b1, baddr);
            #pragma unroll
            for (int mt = 0; mt < 4; ++mt)
                mma16(acc[mt][nt], a[mt][0], a[mt][1], a[mt][2], a[mt][3], b0, b1);
        }
    }
}

__device__ __forceinline__ void zero_acc(float (&acc)[4][4][4]) {
    #pragma unroll
    for (int mt = 0; mt < 4; ++mt)
        #pragma unroll
        for (int nt = 0; nt < 4; ++nt)
            #pragma unroll
            for (int q = 0; q < 4; ++q) acc[mt][nt][q] = 0.f;
}

// ---------------- fused multi-output GEMM (QKV): C_j = A @ W_j, KD=128 ------
// A fp16, C fp16.
__global__ __launch_bounds__(256, 2)
void gemm3_kernel(const __half* __restrict__ A,
                  const __half* __restrict__ W0, const __half* __restrict__ W1,
                  const __half* __restrict__ W2,
                  __half* __restrict__ C0, __half* __restrict__ C1,
                  __half* __restrict__ C2, int M) {
    extern __shared__ __half smh[];
    __half* As = smh;
    __half* Wb0 = smh + AS_HALFS;
    __half* Wb1 = smh + AS_HALFS + WB_HALFS;
    int tid = threadIdx.x;
    int lane = tid & 31, wid = tid >> 5, wm = wid >> 2, wn = wid & 3;
    int m0 = blockIdx.x * 128;

    const __half* Wl[3] = {W0, W1, W2};
    __half* Cl[3] = {C0, C1, C2};
    int nW = W1 ? (W2 ? 3 : 2) : 1;
    int T = nW * 2;

    load_A_cp(As, A, m0, 0, 128, M, tid);
    load_W_cp(Wb0, Wl[0], 0, 0, 128, tid);
    cp_commit();

    float acc[4][4][4];
    for (int t = 0; t < T; ++t) {
        int j = t >> 1, c = t & 1;
        if (c == 0) zero_acc(acc);
        if (t + 1 < T) {
            int j1 = (t + 1) >> 1, c1 = (t + 1) & 1;
            load_W_cp((t & 1) ? Wb0 : Wb1, Wl[j1], c1 * 64, 0, 128, tid);
            cp_commit();
            cp_wait<1>();
        } else {
            cp_wait<0>();
        }
        __syncthreads();
        mma_h64(acc, As, (t & 1) ? Wb1 : Wb0, c * 64, lane, wm, wn);
        __syncthreads();
        if (c == 1) {
            __half* C = Cl[j];
            #pragma unroll
            for (int mt = 0; mt < 4; ++mt) {
                int r0 = m0 + wm * 64 + mt * 16 + (lane >> 2);
                #pragma unroll
                for (int nt = 0; nt < 4; ++nt) {
                    int col = wn * 32 + nt * 8 + (lane & 3) * 2;
                    if (r0 < M)
                        *(unsigned*)(C + (size_t)r0 * 128 + col) =
                            pack_h2(acc[mt][nt][0], acc[mt][nt][1]);
                    if (r0 + 8 < M)
                        *(unsigned*)(C + (size_t)(r0 + 8) * 128 + col) =
                            pack_h2(acc[mt][nt][2], acc[mt][nt][3]);
                }
            }
        }
    }
}

// ---------------- GEMM + bias + residual + LayerNorm fused ------------------
// Y = LN(R + A@W + bias) * g + be.  A, R, Y fp16; math fp32. ND = 128.
template <int KD>
__global__ __launch_bounds__(256, 2)
void gemm_ln_kernel(const __half* __restrict__ A, const __half* __restrict__ W,
                    const float* __restrict__ bias, const __half* __restrict__ R,
                    const float* __restrict__ g, const float* __restrict__ be,
                    __half* __restrict__ Y, int M) {
    extern __shared__ __half smh[];
    __half* As = smh;
    __half* Wb0 = smh + AS_HALFS;
    __half* Wb1 = smh + AS_HALFS + WB_HALFS;
    int tid = threadIdx.x;
    int lane = tid & 31, wid = tid >> 5, wm = wid >> 2, wn = wid & 3;
    int m0 = blockIdx.x * 128;
    constexpr int T = KD / 64;

    float acc[4][4][4];
    zero_acc(acc);

    load_A_cp(As, A, m0, 0, KD, M, tid);
    load_W_cp(Wb0, W, 0, 0, 128, tid);
    cp_commit();

    #pragma unroll
    for (int t = 0; t < T; ++t) {
        if (t + 1 < T) {
            load_W_cp((t & 1) ? Wb0 : Wb1, W, (t + 1) * 64, 0, 128, tid);
            cp_commit();
        }
        if (KD == 256 && t == 2) {   // restage A cols 128..255 (sync of t=1 passed)
            load_A_cp(As, A, m0, 128, KD, M, tid);
            cp_commit();
            cp_wait<0>();
        } else if (t + 1 < T) {
            cp_wait<1>();
        } else {
            cp_wait<0>();
        }
        __syncthreads();
        mma_h64(acc, As, (t & 1) ? Wb1 : Wb0, (t & 1) * 64, lane, wm, wn);
        __syncthreads();
    }

    // Stage pre-LN values into smem as fp32 (stride 132 over whole smem)
    float* Xs = (float*)smh;
    #pragma unroll
    for (int mt = 0; mt < 4; ++mt) {
        int r0 = wm * 64 + mt * 16 + (lane >> 2);
        #pragma unroll
        for (int nt = 0; nt < 4; ++nt) {
            int col = wn * 32 + nt * 8 + (lane & 3) * 2;
            *(float2*)(Xs + r0 * 132 + col) = make_float2(acc[mt][nt][0], acc[mt][nt][1]);
            *(float2*)(Xs + (r0 + 8) * 132 + col) = make_float2(acc[mt][nt][2], acc[mt][nt][3]);
        }
    }
    __syncthreads();

    // LayerNorm: warp per row, 16 rows per warp, lane owns 4 cols.
    int col0 = lane * 4;
    float4 bb4 = *(const float4*)(bias + col0);
    float4 gg = *(const float4*)(g + col0);
    float4 ee = *(const float4*)(be + col0);
    #pragma unroll
    for (int rr = 0; rr < 16; ++rr) {
        int rl = wid * 16 + rr;
        int grow = m0 + rl;
        if (grow >= M) break;
        uint2 ru = *(const uint2*)(R + (size_t)grow * 128 + col0);
        float2 r01 = __half22float2(*(__half2*)&ru.x);
        float2 r23 = __half22float2(*(__half2*)&ru.y);
        float x0 = Xs[rl * 132 + col0 + 0] + bb4.x + r01.x;
        float x1 = Xs[rl * 132 + col0 + 1] + bb4.y + r01.y;
        float x2 = Xs[rl * 132 + col0 + 2] + bb4.z + r23.x;
        float x3 = Xs[rl * 132 + col0 + 3] + bb4.w + r23.y;
        float s = x0 + x1 + x2 + x3;
        #pragma unroll
        for (int o = 16; o > 0; o >>= 1) s += __shfl_xor_sync(0xffffffffu, s, o);
        float mean = s * (1.0f / 128.0f);
        float d0 = x0 - mean, d1 = x1 - mean, d2 = x2 - mean, d3 = x3 - mean;
        float v = d0 * d0 + d1 * d1 + d2 * d2 + d3 * d3;
        #pragma unroll
        for (int o = 16; o > 0; o >>= 1) v += __shfl_xor_sync(0xffffffffu, v, o);
        float rs = rsqrtf(v * (1.0f / 128.0f) + 1e-5f);
        uint2 yo;
        yo.x = pack_h2(fmaf(d0 * rs, gg.x, ee.x), fmaf(d1 * rs, gg.y, ee.y));
        yo.y = pack_h2(fmaf(d2 * rs, gg.z, ee.z), fmaf(d3 * rs, gg.w, ee.w));
        *(uint2*)(Y + (size_t)grow * 128 + col0) = yo;
    }
}

// ---------------- GEMM + bias + ReLU, fp16 out (FFN first layer) -------------
// C[M,256] = relu(A[M,128] @ W + bias). n-chunk via gridDim.y (128 each).
__global__ __launch_bounds__(256, 2)
void gemm_relu_kernel(const __half* __restrict__ A, const __half* __restrict__ W,
                      const float* __restrict__ bias, __half* __restrict__ C,
                      int M, int NDW, int ND) {
    extern __shared__ __half smh[];
    __half* As = smh;
    __half* Wb0 = smh + AS_HALFS;
    __half* Wb1 = smh + AS_HALFS + WB_HALFS;
    int tid = threadIdx.x;
    int lane = tid & 31, wid = tid >> 5, wm = wid >> 2, wn = wid & 3;
    int m0 = blockIdx.x * 128;
    int n0 = blockIdx.y * 128;

    float acc[4][4][4];
    zero_acc(acc);

    load_A_cp(As, A, m0, 0, 128, M, tid);
    load_W_cp(Wb0, W, 0, n0, NDW, tid);
    cp_commit();

    #pragma unroll
    for (int t = 0; t < 2; ++t) {
        if (t == 0) {
            load_W_cp(Wb1, W, 64, n0, NDW, tid);
            cp_commit();
            cp_wait<1>();
        } else {
            cp_wait<0>();
        }
        __syncthreads();
        mma_h64(acc, As, (t & 1) ? Wb1 : Wb0, t * 64, lane, wm, wn);
        __syncthreads();
    }

    #pragma unroll
    for (int mt = 0; mt < 4; ++mt) {
        int r0 = m0 + wm * 64 + mt * 16 + (lane >> 2);
        #pragma unroll
        for (int nt = 0; nt < 4; ++nt) {
            int col = n0 + wn * 32 + nt * 8 + (lane & 3) * 2;
            float b0 = bias[col], b1 = bias[col + 1];
            float v0 = fmaxf(acc[mt][nt][0] + b0, 0.f);
            float v1 = fmaxf(acc[mt][nt][1] + b1, 0.f);
            float v2 = fmaxf(acc[mt][nt][2] + b0, 0.f);
            float v3 = fmaxf(acc[mt][nt][3] + b1, 0.f);
            if (r0 < M)
                *(unsigned*)(C + (size_t)r0 * ND + col) = pack_h2(v0, v1);
            if (r0 + 8 < M)
                *(unsigned*)(C + (size_t)(r0 + 8) * ND + col) = pack_h2(v2, v3);
        }
    }
}

// ---------------- final head: C[M,64] = tanh(A[M,128] @ W4 + b4), fp32 out ---
__global__ __launch_bounds__(256, 2)
void gemm_head_kernel(const __half* __restrict__ A, const __half* __restrict__ W,
                      const float* __restrict__ bias, float* __restrict__ C,
                      int M) {
    extern __shared__ __half smh[];
    __half* As = smh;
    __half* Wb0 = smh + AS_HALFS;
    __half* Wb1 = smh + AS_HALFS + WB_HALFS;
    int tid = threadIdx.x;
    int lane = tid & 31, wid = tid >> 5, wm = wid >> 2, wn = wid & 3;
    int m0 = blockIdx.x * 128;

    float acc[4][4][4];
    zero_acc(acc);

    load_A_cp(As, A, m0, 0, 128, M, tid);
    load_W_cp(Wb0, W, 0, 0, 128, tid);
    cp_commit();

    #pragma unroll
    for (int t = 0; t < 2; ++t) {
        if (t == 0) {
            load_W_cp(Wb1, W, 64, 0, 128, tid);
            cp_commit();
            cp_wait<1>();
        } else {
            cp_wait<0>();
        }
        __syncthreads();
        mma_h64(acc, As, (t & 1) ? Wb1 : Wb0, t * 64, lane, wm, wn);
        __syncthreads();
    }

    #pragma unroll
    for (int mt = 0; mt < 4; ++mt) {
        int r0 = m0 + wm * 64 + mt * 16 + (lane >> 2);
        #pragma unroll
        for (int nt = 0; nt < 4; ++nt) {
            int col = wn * 32 + nt * 8 + (lane & 3) * 2;
            if (col >= 64) continue;   // padded weight region
            float b0 = bias[col], b1 = bias[col + 1];
            float v0 = tanhf(acc[mt][nt][0] + b0);
            float v1 = tanhf(acc[mt][nt][1] + b1);
            float v2 = tanhf(acc[mt][nt][2] + b0);
            float v3 = tanhf(acc[mt][nt][3] + b1);
            if (r0 < M)
                *(float2*)(C + (size_t)r0 * 64 + col) = make_float2(v0, v1);
            if (r0 + 8 < M)
                *(float2*)(C + (size_t)(r0 + 8) * 64 + col) = make_float2(v2, v3);
        }
    }
}

// ---------------- attention: warp per node (fp16 I/O, fp32 math) -------------
__global__ __launch_bounds__(256)
void attn_kernel(const __half* __restrict__ Q, const __half* __restrict__ Kp,
                 const __half* __restrict__ Vp, const int* __restrict__ nbr,
                 __half* __restrict__ O) {
    int node = blockIdx.x * 8 + (threadIdx.x >> 5);
    if (node >= NNODES) return;
    int lane = threadIdx.x & 31;

    uint2 qu = ((const uint2*)(Q + (size_t)node * DMODEL))[lane];
    float2 q01 = __half22float2(*(__half2*)&qu.x);
    float2 q23 = __half22float2(*(__half2*)&qu.y);

    int nidx[KNBR];
    float s[KNBR];
    #pragma unroll
    for (int j = 0; j < KNBR; ++j) {
        int n = nbr[node * KNBR + j];
        nidx[j] = n;
        bool masked = g_mask[node * KNBR + j] != 0;
        uint2 ku = ((const uint2*)(Kp + (size_t)n * DMODEL))[lane];
        float2 k01 = __half22float2(*(__half2*)&ku.x);
        float2 k23 = __half22float2(*(__half2*)&ku.y);
        float d = q01.x * k01.x + q01.y * k01.y + q23.x * k23.x + q23.y * k23.y;
        d += __shfl_xor_sync(0xffffffffu, d, 1);
        d += __shfl_xor_sync(0xffffffffu, d, 2);   // 4-lane (one head) reduce
        s[j] = masked ? -1e30f : d * 0.25f;        // dh^-0.5 = 1/sqrt(16)
    }

    float m = s[0];
    #pragma unroll
    for (int j = 1; j < KNBR; ++j) m = fmaxf(m, s[j]);
    float sum = 0.0f;
    #pragma unroll
    for (int j = 0; j < KNBR; ++j) { s[j] = expf(s[j] - m); sum += s[j]; }
    float inv = 1.0f / sum;

    float a0 = 0.f, a1 = 0.f, a2 = 0.f, a3 = 0.f;
    #pragma unroll
    for (int j = 0; j < KNBR; ++j) {
        float p = s[j] * inv;
        uint2 vu = ((const uint2*)(Vp + (size_t)nidx[j] * DMODEL))[lane];
        float2 v01 = __half22float2(*(__half2*)&vu.x);
        float2 v23 = __half22float2(*(__half2*)&vu.y);
        a0 = fmaf(p, v01.x, a0);
        a1 = fmaf(p, v01.y, a1);
        a2 = fmaf(p, v23.x, a2);
        a3 = fmaf(p, v23.y, a3);
    }
    uint2 ou;
    ou.x = pack_h2(a0, a1);
    ou.y = pack_h2(a2, a3);
    ((uint2*)(O + (size_t)node * DMODEL))[lane] = ou;
}

// ---------------- launch ------------------------------------------------------
extern "C" void kernel_launch(void* const* d_in, const int* in_sizes, int n_in,
                              void* d_out, int out_size) {
    const float* feat = (const float*)d_in[0];
    const int*   nbr  = (const int*)d_in[1];
    const void*  valid = d_in[2];
    const float* wq1 = (const float*)d_in[3];
    const float* wk1 = (const float*)d_in[4];
    const float* wv1 = (const float*)d_in[5];
    const float* wo1 = (const float*)d_in[6];
    const float* bo1 = (const float*)d_in[7];
    const float* w1a = (const float*)d_in[8];
    const float* b1a = (const float*)d_in[9];
    const float* w1b = (const float*)d_in[10];
    const float* b1b = (const float*)d_in[11];
    const float* g1a = (const float*)d_in[12];
    const float* be1a = (const float*)d_in[13];
    const float* g1b = (const float*)d_in[14];
    const float* be1b = (const float*)d_in[15];
    const float* wq2 = (const float*)d_in[16];
    const float* wk2 = (const float*)d_in[17];
    const float* wv2 = (const float*)d_in[18];
    const float* wo2 = (const float*)d_in[19];
    const float* bo2 = (const float*)d_in[20];
    const float* w2a = (const float*)d_in[21];
    const float* b2a = (const float*)d_in[22];
    const float* w2b = (const float*)d_in[23];
    const float* b2b = (const float*)d_in[24];
    const float* g2a = (const float*)d_in[25];
    const float* be2a = (const float*)d_in[26];
    const float* g2b = (const float*)d_in[27];
    const float* be2b = (const float*)d_in[28];
    const float* w4 = (const float*)d_in[29];
    const float* b4 = (const float*)d_in[30];

    cudaFuncSetAttribute(gemm3_kernel,
                         cudaFuncAttributeMaxDynamicSharedMemorySize, SMEM_BYTES);
    cudaFuncSetAttribute(gemm_ln_kernel<128>,
                         cudaFuncAttributeMaxDynamicSharedMemorySize, SMEM_BYTES);
    cudaFuncSetAttribute(gemm_ln_kernel<256>,
                         cudaFuncAttributeMaxDynamicSharedMemorySize, SMEM_BYTES);
    cudaFuncSetAttribute(gemm_relu_kernel,
                         cudaFuncAttributeMaxDynamicSharedMemorySize, SMEM_BYTES);
    cudaFuncSetAttribute(gemm_head_kernel,
                         cudaFuncAttributeMaxDynamicSharedMemorySize, SMEM_BYTES);

    __half *pF, *pQ, *pK, *pV, *pO, *pX1, *pX2, *pH, *pW;
    cudaGetSymbolAddress((void**)&pF, g_featH);
    cudaGetSymbolAddress((void**)&pQ, g_Q);
    cudaGetSymbolAddress((void**)&pK, g_K);
    cudaGetSymbolAddress((void**)&pV, g_V);
    cudaGetSymbolAddress((void**)&pO, g_O);
    cudaGetSymbolAddress((void**)&pX1, g_X1);
    cudaGetSymbolAddress((void**)&pX2, g_X2);
    cudaGetSymbolAddress((void**)&pH, g_H);
    cudaGetSymbolAddress((void**)&pW, g_Wh);

    const int M = NNODES;
    const int GB = (M + 127) / 128;      // tensor-core gemm blocks (BM=128)
    const int GW = (M + 7) / 8;          // warp-per-row blocks
    const int GE = (M * KNBR + 255) / 256;

    detect_valid_kernel<<<1, 1>>>((const unsigned int*)valid);
    prep_feat_kernel<<<GW, 256>>>(feat);
    edgemask_kernel<<<GE, 256>>>(valid, nbr);
    convert_w_kernel<<<dim3(128, 13), 256>>>(wq1, wk1, wv1, wo1, w1a, w1b,
                                             wq2, wk2, wv2, wo2, w2a, w2b, w4);

    // ---- layer 1 ----
    gemm3_kernel<<<GB, 256, SMEM_BYTES>>>(pF, pW + OFF_WQ1, pW + OFF_WK1,
                                          pW + OFF_WV1, pQ, pK, pV, M);
    attn_kernel<<<GW, 256>>>(pQ, pK, pV, nbr, pO);
    gemm_ln_kernel<128><<<GB, 256, SMEM_BYTES>>>(pO, pW + OFF_WO1, bo1, pF,
                                                 g1a, be1a, pX1, M);
    gemm_relu_kernel<<<dim3(GB, 2), 256, SMEM_BYTES>>>(pX1, pW + OFF_W1A, b1a,
                                                       pH, M, 256, 256);
    gemm_ln_kernel<256><<<GB, 256, SMEM_BYTES>>>(pH, pW + OFF_W1B, b1b, pX1,
                                                 g1b, be1b, pX2, M);

    // ---- layer 2 (q from pX2; k/v from feat) ----
    gemm3_kernel<<<GB, 256, SMEM_BYTES>>>(pX2, pW + OFF_WQ2, nullptr, nullptr,
                                          pQ, nullptr, nullptr, M);
    gemm3_kernel<<<GB, 256, SMEM_BYTES>>>(pF, pW + OFF_WK2, pW + OFF_WV2,
                                          nullptr, pK, pV, nullptr, M);
    attn_kernel<<<GW, 256>>>(pQ, pK, pV, nbr, pO);
    gemm_ln_kernel<128><<<GB, 256, SMEM_BYTES>>>(pO, pW + OFF_WO2, bo2, pX2,
                                                 g2a, be2a, pX1, M);
    gemm_relu_kernel<<<dim3(GB, 2), 256, SMEM_BYTES>>>(pX1, pW + OFF_W2A, b2a,
                                                       pH, M, 256, 256);
    gemm_ln_kernel<256><<<GB, 256, SMEM_BYTES>>>(pH, pW + OFF_W2B, b2b, pX1,
                                                 g2b, be2b, pX2, M);

    // ---- final head (tanh, ND=64, padded weight) ----
    gemm_head_kernel<<<GB, 256, SMEM_BYTES>>>(pX2, pW + OFF_W4, b4,
                                              (float*)d_out, M);
}